// round 14
// baseline (speedup 1.0000x reference)
#include <cuda_runtime.h>
#include <cuda_fp16.h>
#include <math.h>
#include <stdint.h>

#define NB 32
#define NT 512
#define NI 1024
#define NH 1024
#define NG 4096
#define GB (NG*NB)              // gate elems per step, layout [t][j'][b]
#define LOFF (4*NH*NI)
#define GRID_BLOCKS 128
#define NK16 64                 // K=1024 in 64 chunks of 16
#define B_B32 16384             // one B vector in b32: 64*4*32*2 (fp16 single)
#define MAT_U4 524288           // uint4 stride per A matrix (4096x1024 fp16)
// smem: sA 8192 u4 (128K) + sTile 2048 f (8K) + sC 512 f (2K)
#define SMEM_BYTES (131072 + 8192 + 2048)
#define PRE_SMEM 32768

// ---------------- device scratch -------------------------------------------
__device__ __align__(256) float g_xg0[(size_t)(NT + 1) * GB]; // [t][j'][b]
// A fragments fp16 in m16n8k16 A layout.
// mats 0-2 (Wh0, Wh1, Wx1): interleaved rows j'=hh*4+g, [blk64][tile4][k16][lane]
// mat 3 (Wx0, pregemm): original rows, [blk32][warp8][k16][lane]
__device__ __align__(128) __half g_Ahi[(size_t)4 * 4096 * 1024];
__device__ __align__(128) __half g_Alo[(size_t)4 * 4096 * 1024];
// seq B-fragments (hi only)
__device__ __align__(128) __half g_Sh[(size_t)64 * 2048 * 128];
// h B-fragments (single fp16), double-buffered by parity
__device__ __align__(128) uint32_t g_B0[2][B_B32];
__device__ __align__(128) uint32_t g_B1[2][B_B32];
// Wx1 @ h0 partial gate sums, double-buffered by parity: [p][j'][b]
__device__ __align__(256) float g_part[2][NG * NB];
__device__ unsigned g_bar_count;

// ---------------------------------------------------------------------------
__global__ void init_state() {
    int i = blockIdx.x * blockDim.x + threadIdx.x;
    int n = gridDim.x * blockDim.x;
    for (int k = i; k < B_B32; k += n) {
        g_B0[0][k] = 0u; g_B0[1][k] = 0u;
        g_B1[0][k] = 0u; g_B1[1][k] = 0u;
    }
    if (i == 0) g_bar_count = 0;
}

// ---------------------------------------------------------------------------
__global__ __launch_bounds__(256) void prep_weights(const float* __restrict__ Wh,
                                                    const float* __restrict__ Wx) {
    size_t i = (size_t)blockIdx.x * 256 + threadIdx.x;   // 0 .. 4*4M-1
    int r = (int)(i >> 22);
    int rem = (int)(i & 4194303);
    const float* src = (r == 0) ? Wh : (r == 1) ? (Wh + LOFF)
                     : (r == 2) ? (Wx + LOFF) : Wx;
    float w = src[rem];
    __half hi = __float2half_rn(w);
    __half lo = __float2half_rn(w - __half2float(hi));
    int j = rem >> 10;           // original row g*1024+hh
    int k = rem & 1023;
    int k16 = k >> 4;
    int kc = k & 15;
    size_t frag;
    if (r == 3) {
        int blk = j >> 7, wrp = (j >> 4) & 7, row16 = j & 15;
        int lane = (row16 & 7) * 4 + ((kc & 7) >> 1);
        frag = ((size_t)(blk * 8 + wrp) * 64 + k16) * 32 + lane;
        int reg = ((kc >= 8) ? 2 : 0) + ((row16 >= 8) ? 1 : 0);
        size_t bidx = (frag * 4 + reg) * 2 + (kc & 1) + (size_t)r * 4194304;
        g_Ahi[bidx] = hi; g_Alo[bidx] = lo;
        return;
    }
    int g = j >> 10, hh = j & 1023;
    int jp = hh * 4 + g;
    int row16 = jp & 15;
    int lane = (row16 & 7) * 4 + ((kc & 7) >> 1);
    int reg = ((kc >= 8) ? 2 : 0) + ((row16 >= 8) ? 1 : 0);
    int blk = jp >> 6, tile = (jp >> 4) & 3;
    frag = ((size_t)(blk * 4 + tile) * 64 + k16) * 32 + lane;
    size_t bidx = (frag * 4 + reg) * 2 + (kc & 1) + (size_t)r * 4194304;
    g_Ahi[bidx] = hi; g_Alo[bidx] = lo;
}

// ---------------------------------------------------------------------------
__global__ __launch_bounds__(256) void prep_seq(const float* __restrict__ seq) {
    size_t i = (size_t)blockIdx.x * 256 + threadIdx.x;
    float v = seq[i];
    __half hi = __float2half_rn(v);
    int b = (int)(i >> 19);
    int t = (int)(i >> 10) & 511;
    int k = (int)i & 1023;
    int c = t * 32 + b;
    int k16 = k >> 4, kc = k & 15;
    int n8 = c >> 3, nc = c & 7;
    int lane = nc * 4 + ((kc & 7) >> 1);
    int reg = (kc >= 8) ? 1 : 0;
    size_t idx = ((((size_t)k16 * 2048 + n8) * 32 + lane) * 2 + reg) * 2 + (kc & 1);
    g_Sh[idx] = hi;
}

// ---------------------------------------------------------------------------
__device__ __forceinline__ void mma_f16(float* d, const uint4& a,
                                        uint32_t b0, uint32_t b1) {
    asm volatile(
        "mma.sync.aligned.m16n8k16.row.col.f32.f16.f16.f32 "
        "{%0,%1,%2,%3},{%4,%5,%6,%7},{%8,%9},{%0,%1,%2,%3};"
        : "+f"(d[0]), "+f"(d[1]), "+f"(d[2]), "+f"(d[3])
        : "r"(a.x), "r"(a.y), "r"(a.z), "r"(a.w), "r"(b0), "r"(b1));
}
__device__ __forceinline__ uint32_t smem_u32(const void* p) {
    uint32_t a;
    asm("{ .reg .u64 t; cvta.to.shared.u64 t, %1; cvt.u32.u64 %0, t; }"
        : "=r"(a) : "l"(p));
    return a;
}

// ---------------------------------------------------------------------------
// Pregemm: xg0[t][j'][b] = Wx0 @ x, fp16 2-pass (A hi/lo, B single fp16).
// ---------------------------------------------------------------------------
__global__ __launch_bounds__(256) void pregemm_mma() {
    extern __shared__ uint32_t sm[];
    uint32_t* sBh = sm;

    int tid = threadIdx.x;
    int lane = tid & 31;
    int wrp = tid >> 5;
    int blkM = blockIdx.x;
    int blkN = blockIdx.y;

    const uint4* Ah_w = (const uint4*)g_Ahi + 3 * MAT_U4 +
        (size_t)(blkM * 8 + wrp) * NK16 * 32;
    const uint4* Al_w = (const uint4*)g_Alo + 3 * MAT_U4 +
        (size_t)(blkM * 8 + wrp) * NK16 * 32;
    const uint4* gSh = (const uint4*)g_Sh;

    float acc[16][4];
#pragma unroll
    for (int nn = 0; nn < 16; nn++)
#pragma unroll
        for (int q = 0; q < 4; q++) acc[nn][q] = 0.0f;

    for (int kc8 = 0; kc8 < 8; kc8++) {
#pragma unroll
        for (int it = 0; it < 8; it++) {
            int flat = it * 256 + tid;
            int kk = flat >> 8;
            int rem = flat & 255;
            int nn = rem >> 4;
            int q = rem & 15;
            size_t srcu4 = ((size_t)(kc8 * 8 + kk) * 2048 + blkN * 16 + nn) * 16 + q;
            ((uint4*)sBh)[flat] = gSh[srcu4];
        }
        __syncthreads();
#pragma unroll 2
        for (int kk = 0; kk < 8; kk++) {
            int k16 = kc8 * 8 + kk;
            uint4 ah = Ah_w[k16 * 32 + lane];
            uint4 al = Al_w[k16 * 32 + lane];
#pragma unroll
            for (int nn = 0; nn < 16; nn++) {
                int bix = ((kk * 16 + nn) * 32 + lane) * 2;
                mma_f16(acc[nn], ah, sBh[bix], sBh[bix + 1]);
            }
#pragma unroll
            for (int nn = 0; nn < 16; nn++) {
                int bix = ((kk * 16 + nn) * 32 + lane) * 2;
                mma_f16(acc[nn], al, sBh[bix], sBh[bix + 1]);
            }
        }
        __syncthreads();
    }
    int j0a = blkM * 128 + wrp * 16 + (lane >> 2);
    int j0b = j0a + 8;
    int ja = (j0a & 1023) * 4 + (j0a >> 10);
    int jb = (j0b & 1023) * 4 + (j0b >> 10);
    int ccl = (lane & 3) * 2;
#pragma unroll
    for (int nn = 0; nn < 16; nn++) {
        int c = blkN * 128 + nn * 8 + ccl;
        int t = c >> 5;
        int b = c & 31;
        float* base = g_xg0 + (size_t)t * GB + b;
        *(float2*)(base + (size_t)ja * 32) = make_float2(acc[nn][0], acc[nn][1]);
        *(float2*)(base + (size_t)jb * 32) = make_float2(acc[nn][2], acc[nn][3]);
    }
}

// ---------------------------------------------------------------------------
__device__ __forceinline__ float sigf(float x) {
    return 1.0f / (1.0f + __expf(-x));
}
__device__ __forceinline__ float tanhfast(float x) {
    return 2.0f / (1.0f + __expf(-2.0f * x)) - 1.0f;
}

// monotonic grid barrier: REDG arrival (no return), acquire-poll by tid 0
__device__ __forceinline__ void grid_sync(unsigned& target) {
    __syncthreads();
    target += GRID_BLOCKS;
    if (threadIdx.x == 0) {
        asm volatile("red.release.gpu.global.add.u32 [%0], %1;"
                     :: "l"(&g_bar_count), "r"(1u) : "memory");
        unsigned v;
        do {
            asm volatile("ld.acquire.gpu.global.u32 %0, [%1];"
                         : "=r"(v) : "l"(&g_bar_count) : "memory");
        } while (v < target);
    }
    __syncthreads();
}

// write h (single fp16) into B-fragment layout
__device__ __forceinline__ void store_h(uint32_t* bdst, int b, int hh, float hn) {
    int k16 = hh >> 4;
    int kc = hh & 15;
    int n8 = b >> 3;
    int nc = b & 7;
    int lane = nc * 4 + ((kc & 7) >> 1);
    int reg = (kc >= 8) ? 1 : 0;
    size_t bidx = (size_t)(((k16 * 4 + n8) * 32 + lane) * 2 + reg) * 2 + (kc & 1);
    ((__half*)bdst)[bidx] = __float2half_rn(hn);
}

// swap register-index bit (1<<R) of v[16] with lane bit (1<<L)
template <int R, int L>
__device__ __forceinline__ void frag_swap(float* v, int lane) {
    bool a = (lane >> L) & 1;
#pragma unroll
    for (int i = 0; i < 16; i++) {
        if (i & (1 << R)) continue;
        int j = i | (1 << R);
        float send = a ? v[i] : v[j];
        float got = __shfl_xor_sync(0xffffffffu, send, 1 << L);
        if (a) v[i] = got; else v[j] = got;
    }
}

// ---------------------------------------------------------------------------
// Persistent LSTM: 128 blocks x 256 threads, monotonic REDG barrier, 513
// rounds, L1 lags L0 by one round.  B operands are read DIRECTLY from L2
// (no smem staging): all blocks of a region broadcast-read the same 64 KB
// fragment buffer; each fragment is consumed once per warp, so staging
// added latency with zero reuse benefit.
//   L0 (bid 0..63): round n: warps 0-3 Wh0 (pinned SMEM) @ h0(n) [LDG B] ->
//     shuffle-transpose -> in-register cell update -> h0(n+1);
//     warps 4-7 Wx1 (streamed) @ h0(n) [LDG B] -> g_part[n&1].
//   L1 (bid 64..127): round s, m=s-1: Wh1 (pinned) @ h1(m-1) [LDG B] ->
//     sTile combine; gates = sTile + g_part[m&1] + bias -> h1(m).
// ---------------------------------------------------------------------------
__global__ __launch_bounds__(256, 1) void lstm_persist(
    const float* __restrict__ Bias, float* __restrict__ out) {
    extern __shared__ uint32_t sm[];
    uint4* sA = (uint4*)sm;                      // 8192 u4 = 128 KB pinned A
    float* sTile = (float*)(sm + 32768);         // 2048 f32 (L1 only)
    float* sC = sTile + 2048;                    // 512 f32  (L1 only)

    int tid = threadIdx.x;
    int lane = tid & 31;
    int wrp = tid >> 5;
    int bid = blockIdx.x;
    int region = (bid < 64) ? 0 : 1;
    int blk = bid & 63;

    // preload pinned A slice (mat0=Wh0 for L0, mat1=Wh1 for L1), 8192 uint4
    {
        const uint4* Apin = (const uint4*)g_Ahi +
            (size_t)region * MAT_U4 + (size_t)(blk * 4) * NK16 * 32;
        for (int i = tid; i < 8192; i += 256) sA[i] = Apin[i];
    }

    int tile = wrp & 3;
    int mat = wrp >> 2;   // L0: 0=Wh0 (pinned), 1=Wx1 (streamed); L1: khalf

    const uint4* A2 = (const uint4*)g_Ahi + 2 * MAT_U4 +
        (size_t)(blk * 4 + tile) * NK16 * 32;    // Wx1 slice (L0 warps 4-7)

    unsigned target = 0;

    if (region == 0) {
        // ------------------------------ LAYER 0 ------------------------------
        int colb = ((lane >> 2) & 3) * 8 + (lane & 3) * 2;
        float bgr[4][2];
        float creg[4];
        if (mat == 0) {
#pragma unroll
            for (int g = 0; g < 4; g++)
#pragma unroll
                for (int h2 = 0; h2 < 2; h2++) {
                    int hh_l = tile * 4 + (lane >> 4) + 2 * h2;
                    bgr[g][h2] = Bias[g * 1024 + blk * 16 + hh_l];
                }
            // prologue: h0(0) = cell(c=0, xg0[0] + bias) -> g_B0[0]
            const float* xg = g_xg0 + (size_t)(blk * 64) * 32;
#pragma unroll
            for (int h2 = 0; h2 < 2; h2++) {
                int hh_l = tile * 4 + (lane >> 4) + 2 * h2;
#pragma unroll
                for (int cp = 0; cp < 2; cp++) {
                    int col = colb + cp;
                    float w = xg[(4 * hh_l + 1) * 32 + col] + bgr[1][h2];
                    float i_ = xg[(4 * hh_l + 2) * 32 + col] + bgr[2][h2];
                    float o = xg[(4 * hh_l + 3) * 32 + col] + bgr[3][h2];
                    float cn = sigf(w) * tanhfast(i_);
                    float hn = tanhfast(cn) * sigf(o);
                    creg[h2 * 2 + cp] = cn;
                    store_h(g_B0[0], col, blk * 16 + hh_l, hn);
                }
            }
        }

        for (int n = 0; n < NT; n++) {
            // PRE-barrier: prefetch next-step input gates (static data)
            float2 xr2[8];
            if (mat == 0 && n < NT - 1) {
                const float* xg = g_xg0 + (size_t)(n + 1) * GB +
                                  (size_t)(blk * 64) * 32;
#pragma unroll
                for (int g = 0; g < 4; g++)
#pragma unroll
                    for (int h2 = 0; h2 < 2; h2++) {
                        int hh_l = tile * 4 + (lane >> 4) + 2 * h2;
                        xr2[g * 2 + h2] =
                            *(const float2*)(xg + (size_t)(4 * hh_l + g) * 32 + colb);
                    }
            }
            grid_sync(target);
            int p = n & 1;
            const uint2* gB = (const uint2*)g_B0[p] + lane;   // B direct from L2

            float accf[16];
#pragma unroll
            for (int i = 0; i < 16; i++) accf[i] = 0.0f;

            if (mat == 0) {
                if (n < NT - 1) {
#pragma unroll 8
                    for (int k16 = 0; k16 < NK16; k16++) {
                        uint4 a = sA[(tile * 64 + k16) * 32 + lane];
#pragma unroll
                        for (int nt = 0; nt < 4; nt++) {
                            uint2 bv = __ldg(gB + (k16 * 4 + nt) * 32);
                            mma_f16(&accf[nt * 4], a, bv.x, bv.y);
                        }
                    }
                    // shuffle-transpose: reg bits 2,3 (nt) <-> lane bits 2,3 (g)
                    frag_swap<2, 2>(accf, lane);
                    frag_swap<3, 3>(accf, lane);
                    // in-register cell update -> h0(n+1)
#pragma unroll
                    for (int q = 0; q < 4; q++) {
                        int h2 = q >> 1, cp = q & 1;
                        int hh_l = tile * 4 + (lane >> 4) + 2 * h2;
                        int col = colb + cp;
                        float xf = cp ? xr2[0 * 2 + h2].y : xr2[0 * 2 + h2].x;
                        float xw = cp ? xr2[1 * 2 + h2].y : xr2[1 * 2 + h2].x;
                        float xi = cp ? xr2[2 * 2 + h2].y : xr2[2 * 2 + h2].x;
                        float xo = cp ? xr2[3 * 2 + h2].y : xr2[3 * 2 + h2].x;
                        float f = accf[0 + q] + xf + bgr[0][h2];
                        float w = accf[4 + q] + xw + bgr[1][h2];
                        float i_ = accf[8 + q] + xi + bgr[2][h2];
                        float o = accf[12 + q] + xo + bgr[3][h2];
                        float cv = creg[q];
                        float cn = cv * sigf(f) + sigf(w) * tanhfast(i_);
                        float hn = tanhfast(cn) * sigf(o);
                        creg[q] = cn;
                        store_h(g_B0[(n + 1) & 1], col, blk * 16 + hh_l, hn);
                    }
                }
            } else {
                // Wx1 @ h0(n) -> partial gates for L1 next round
#pragma unroll 8
                for (int k16 = 0; k16 < NK16; k16++) {
                    uint4 a = A2[k16 * 32 + lane];
#pragma unroll
                    for (int nt = 0; nt < 4; nt++) {
                        uint2 bv = __ldg(gB + (k16 * 4 + nt) * 32);
                        mma_f16(&accf[nt * 4], a, bv.x, bv.y);
                    }
                }
                int r0 = tile * 16 + (lane >> 2);
                int cc = (lane & 3) * 2;
                float* gp = g_part[p] + (size_t)(blk * 64) * 32;
#pragma unroll
                for (int nt = 0; nt < 4; nt++) {
                    *(float2*)(gp + (size_t)r0 * 32 + nt * 8 + cc) =
                        make_float2(accf[nt * 4 + 0], accf[nt * 4 + 1]);
                    *(float2*)(gp + (size_t)(r0 + 8) * 32 + nt * 8 + cc) =
                        make_float2(accf[nt * 4 + 2], accf[nt * 4 + 3]);
                }
            }
            __syncthreads();
        }
        grid_sync(target);                       // round s = NT (L1 finishes)
    } else {
        // ------------------------------ LAYER 1 ------------------------------
        float bf[2], bw[2], bi_[2], bo[2];
#pragma unroll
        for (int i = 0; i < 2; i++) {
            int hh = blk * 16 + ((tid + i * 256) >> 5);
            bf[i] = Bias[4096 + hh];        bw[i] = Bias[4096 + 1024 + hh];
            bi_[i] = Bias[4096 + 2048 + hh]; bo[i] = Bias[4096 + 3072 + hh];
        }
#pragma unroll
        for (int i = 0; i < 2; i++) sC[tid + i * 256] = 0.0f;
        __syncthreads();

        for (int s = 0; s <= NT; s++) {
            grid_sync(target);
            if (s < 1) continue;
            int m = s - 1;
            if (m >= 1) {
                const uint2* gB = (const uint2*)g_B1[(m - 1) & 1] + lane;

                float accf[16];
#pragma unroll
                for (int i = 0; i < 16; i++) accf[i] = 0.0f;
#pragma unroll 8
                for (int kk = 0; kk < 32; kk++) {
                    int k16 = mat * 32 + kk;
                    uint4 a = sA[(tile * 64 + k16) * 32 + lane];
#pragma unroll
                    for (int nt = 0; nt < 4; nt++) {
                        uint2 bv = __ldg(gB + (k16 * 4 + nt) * 32);
                        mma_f16(&accf[nt * 4], a, bv.x, bv.y);
                    }
                }
                // combine K-halves in sTile
                int r0 = tile * 16 + (lane >> 2);
                int cc = (lane & 3) * 2;
                if (mat == 0) {
#pragma unroll
                    for (int nt = 0; nt < 4; nt++) {
                        *(float2*)&sTile[r0 * 32 + nt * 8 + cc] =
                            make_float2(accf[nt * 4 + 0], accf[nt * 4 + 1]);
                        *(float2*)&sTile[(r0 + 8) * 32 + nt * 8 + cc] =
                            make_float2(accf[nt * 4 + 2], accf[nt * 4 + 3]);
                    }
                }
                __syncthreads();
                if (mat == 1) {
#pragma unroll
                    for (int nt = 0; nt < 4; nt++) {
                        float2* p0 = (float2*)&sTile[r0 * 32 + nt * 8 + cc];
                        float2* p1 = (float2*)&sTile[(r0 + 8) * 32 + nt * 8 + cc];
                        float2 v0 = *p0, v1 = *p1;
                        v0.x += accf[nt * 4 + 0]; v0.y += accf[nt * 4 + 1];
                        v1.x += accf[nt * 4 + 2]; v1.y += accf[nt * 4 + 3];
                        *p0 = v0; *p1 = v1;
                    }
                }
                __syncthreads();
            } else {
                // m == 0: h1(-1) = 0, recurrent term vanishes
                for (int i = tid; i < 2048; i += 256) sTile[i] = 0.0f;
                __syncthreads();
            }
            // fused cell update: gates = sTile + partial(m) + bias -> h1(m)
            const float* gp = g_part[m & 1] + (size_t)(blk * 64) * 32;
#pragma unroll
            for (int i = 0; i < 2; i++) {
                int q = tid + i * 256;
                int hh_l = q >> 5, b = q & 31, br = hh_l * 4;
                float f = sTile[br * 32 + b] + gp[br * 32 + b] + bf[i];
                float w = sTile[(br + 1) * 32 + b] + gp[(br + 1) * 32 + b] + bw[i];
                float i_ = sTile[(br + 2) * 32 + b] + gp[(br + 2) * 32 + b] + bi_[i];
                float o = sTile[(br + 3) * 32 + b] + gp[(br + 3) * 32 + b] + bo[i];
                float cv = sC[q];
                float cn = cv * sigf(f) + sigf(w) * tanhfast(i_);
                float hn = tanhfast(cn) * sigf(o);
                sC[q] = cn;
                store_h(g_B1[m & 1], b, blk * 16 + hh_l, hn);
                if (m == NT - 1) out[b * 1024 + blk * 16 + hh_l] = hn;
            }
            __syncthreads();
        }
    }
}

// ---------------------------------------------------------------------------
extern "C" void kernel_launch(void* const* d_in, const int* in_sizes, int n_in,
                              void* d_out, int out_size) {
    const float* seq  = (const float*)d_in[0];  // (32, 512, 1024)
    const float* Wh   = (const float*)d_in[1];  // (2, 4, 1024, 1024)
    const float* Wx   = (const float*)d_in[2];  // (2, 4, 1024, 1024)
    const float* Bias = (const float*)d_in[3];  // (2, 4, 1024)
    float* out = (float*)d_out;                 // (32, 1024)

    cudaFuncSetAttribute(lstm_persist,
                         cudaFuncAttributeMaxDynamicSharedMemorySize, SMEM_BYTES);
    cudaFuncSetAttribute(pregemm_mma,
                         cudaFuncAttributeMaxDynamicSharedMemorySize, PRE_SMEM);

    init_state<<<64, 256>>>();
    prep_weights<<<4 * 4096 * 1024 / 256, 256>>>(Wh, Wx);
    prep_seq<<<NB * NT * NI / 256, 256>>>(seq);
    pregemm_mma<<<dim3(32, 128), 256, PRE_SMEM>>>();
    lstm_persist<<<GRID_BLOCKS, 256, SMEM_BYTES>>>(Bias, out);
}

// round 15
// speedup vs baseline: 1.0992x; 1.0992x over previous
#include <cuda_runtime.h>
#include <cuda_fp16.h>
#include <math.h>
#include <stdint.h>

#define NB 32
#define NT 512
#define NI 1024
#define NH 1024
#define NG 4096
#define GB (NG*NB)              // gate elems per step, layout [t][j'][b]
#define LOFF (4*NH*NI)
#define GRID_BLOCKS 128
#define NK16 64                 // K=1024 in 64 chunks of 16
#define B_B32 16384             // one B vector in b32: 64*4*32*2 (fp16 single)
#define MAT_U4 524288           // uint4 stride per A matrix (4096x1024 fp16)
// smem: sA 8192 u4 (128K) + sB 16384 b32 (64K) + sComb 2048 f (8K)
#define SMEM_BYTES (131072 + 65536 + 8192)
#define PRE_SMEM 32768

// ---------------- device scratch -------------------------------------------
__device__ __align__(256) float g_xg0[(size_t)(NT + 1) * GB]; // [t][j'][b]
// A fragments fp16 in m16n8k16 A layout.
// mats 0-2 (Wh0, Wh1, Wx1): interleaved rows j'=hh*4+g, [blk64][tile4][k16][lane]
// mat 3 (Wx0, pregemm): original rows, [blk32][warp8][k16][lane]
__device__ __align__(128) __half g_Ahi[(size_t)4 * 4096 * 1024];
__device__ __align__(128) __half g_Alo[(size_t)4 * 4096 * 1024];
// seq B-fragments (hi only)
__device__ __align__(128) __half g_Sh[(size_t)64 * 2048 * 128];
// h B-fragments (single fp16), double-buffered by parity
__device__ __align__(128) uint32_t g_B0[2][B_B32];
__device__ __align__(128) uint32_t g_B1[2][B_B32];
// Wx1 @ h0 partial gate sums, double-buffered by parity: [p][j'][b]
__device__ __align__(256) float g_part[2][NG * NB];
__device__ unsigned g_bar_count;

// ---------------------------------------------------------------------------
__global__ void init_state() {
    int i = blockIdx.x * blockDim.x + threadIdx.x;
    int n = gridDim.x * blockDim.x;
    for (int k = i; k < B_B32; k += n) {
        g_B0[0][k] = 0u; g_B0[1][k] = 0u;
        g_B1[0][k] = 0u; g_B1[1][k] = 0u;
    }
    if (i == 0) g_bar_count = 0;
}

// ---------------------------------------------------------------------------
__global__ __launch_bounds__(256) void prep_weights(const float* __restrict__ Wh,
                                                    const float* __restrict__ Wx) {
    size_t i = (size_t)blockIdx.x * 256 + threadIdx.x;   // 0 .. 4*4M-1
    int r = (int)(i >> 22);
    int rem = (int)(i & 4194303);
    const float* src = (r == 0) ? Wh : (r == 1) ? (Wh + LOFF)
                     : (r == 2) ? (Wx + LOFF) : Wx;
    float w = src[rem];
    __half hi = __float2half_rn(w);
    __half lo = __float2half_rn(w - __half2float(hi));
    int j = rem >> 10;           // original row g*1024+hh
    int k = rem & 1023;
    int k16 = k >> 4;
    int kc = k & 15;
    size_t frag;
    if (r == 3) {
        int blk = j >> 7, wrp = (j >> 4) & 7, row16 = j & 15;
        int lane = (row16 & 7) * 4 + ((kc & 7) >> 1);
        frag = ((size_t)(blk * 8 + wrp) * 64 + k16) * 32 + lane;
        int reg = ((kc >= 8) ? 2 : 0) + ((row16 >= 8) ? 1 : 0);
        size_t bidx = (frag * 4 + reg) * 2 + (kc & 1) + (size_t)r * 4194304;
        g_Ahi[bidx] = hi; g_Alo[bidx] = lo;
        return;
    }
    int g = j >> 10, hh = j & 1023;
    int jp = hh * 4 + g;
    int row16 = jp & 15;
    int lane = (row16 & 7) * 4 + ((kc & 7) >> 1);
    int reg = ((kc >= 8) ? 2 : 0) + ((row16 >= 8) ? 1 : 0);
    int blk = jp >> 6, tile = (jp >> 4) & 3;
    frag = ((size_t)(blk * 4 + tile) * 64 + k16) * 32 + lane;
    size_t bidx = (frag * 4 + reg) * 2 + (kc & 1) + (size_t)r * 4194304;
    g_Ahi[bidx] = hi; g_Alo[bidx] = lo;
}

// ---------------------------------------------------------------------------
__global__ __launch_bounds__(256) void prep_seq(const float* __restrict__ seq) {
    size_t i = (size_t)blockIdx.x * 256 + threadIdx.x;
    float v = seq[i];
    __half hi = __float2half_rn(v);
    int b = (int)(i >> 19);
    int t = (int)(i >> 10) & 511;
    int k = (int)i & 1023;
    int c = t * 32 + b;
    int k16 = k >> 4, kc = k & 15;
    int n8 = c >> 3, nc = c & 7;
    int lane = nc * 4 + ((kc & 7) >> 1);
    int reg = (kc >= 8) ? 1 : 0;
    size_t idx = ((((size_t)k16 * 2048 + n8) * 32 + lane) * 2 + reg) * 2 + (kc & 1);
    g_Sh[idx] = hi;
}

// ---------------------------------------------------------------------------
__device__ __forceinline__ void mma_f16(float* d, const uint4& a,
                                        uint32_t b0, uint32_t b1) {
    asm volatile(
        "mma.sync.aligned.m16n8k16.row.col.f32.f16.f16.f32 "
        "{%0,%1,%2,%3},{%4,%5,%6,%7},{%8,%9},{%0,%1,%2,%3};"
        : "+f"(d[0]), "+f"(d[1]), "+f"(d[2]), "+f"(d[3])
        : "r"(a.x), "r"(a.y), "r"(a.z), "r"(a.w), "r"(b0), "r"(b1));
}
__device__ __forceinline__ uint32_t smem_u32(const void* p) {
    uint32_t a;
    asm("{ .reg .u64 t; cvta.to.shared.u64 t, %1; cvt.u32.u64 %0, t; }"
        : "=r"(a) : "l"(p));
    return a;
}
__device__ __forceinline__ void cp16(uint32_t dst, const void* src) {
    asm volatile("cp.async.cg.shared.global [%0], [%1], 16;"
                 :: "r"(dst), "l"(src));
}
#define CP_COMMIT() asm volatile("cp.async.commit_group;")
#define CP_WAIT0()  asm volatile("cp.async.wait_group 0;")

// ---------------------------------------------------------------------------
// Pregemm: xg0[t][j'][b] = Wx0 @ x, fp16 2-pass (A hi/lo, B single fp16).
// ---------------------------------------------------------------------------
__global__ __launch_bounds__(256) void pregemm_mma() {
    extern __shared__ uint32_t sm[];
    uint32_t* sBh = sm;

    int tid = threadIdx.x;
    int lane = tid & 31;
    int wrp = tid >> 5;
    int blkM = blockIdx.x;
    int blkN = blockIdx.y;

    const uint4* Ah_w = (const uint4*)g_Ahi + 3 * MAT_U4 +
        (size_t)(blkM * 8 + wrp) * NK16 * 32;
    const uint4* Al_w = (const uint4*)g_Alo + 3 * MAT_U4 +
        (size_t)(blkM * 8 + wrp) * NK16 * 32;
    const uint4* gSh = (const uint4*)g_Sh;

    float acc[16][4];
#pragma unroll
    for (int nn = 0; nn < 16; nn++)
#pragma unroll
        for (int q = 0; q < 4; q++) acc[nn][q] = 0.0f;

    for (int kc8 = 0; kc8 < 8; kc8++) {
#pragma unroll
        for (int it = 0; it < 8; it++) {
            int flat = it * 256 + tid;
            int kk = flat >> 8;
            int rem = flat & 255;
            int nn = rem >> 4;
            int q = rem & 15;
            size_t srcu4 = ((size_t)(kc8 * 8 + kk) * 2048 + blkN * 16 + nn) * 16 + q;
            ((uint4*)sBh)[flat] = gSh[srcu4];
        }
        __syncthreads();
#pragma unroll 2
        for (int kk = 0; kk < 8; kk++) {
            int k16 = kc8 * 8 + kk;
            uint4 ah = Ah_w[k16 * 32 + lane];
            uint4 al = Al_w[k16 * 32 + lane];
#pragma unroll
            for (int nn = 0; nn < 16; nn++) {
                int bix = ((kk * 16 + nn) * 32 + lane) * 2;
                mma_f16(acc[nn], ah, sBh[bix], sBh[bix + 1]);
            }
#pragma unroll
            for (int nn = 0; nn < 16; nn++) {
                int bix = ((kk * 16 + nn) * 32 + lane) * 2;
                mma_f16(acc[nn], al, sBh[bix], sBh[bix + 1]);
            }
        }
        __syncthreads();
    }
    int j0a = blkM * 128 + wrp * 16 + (lane >> 2);
    int j0b = j0a + 8;
    int ja = (j0a & 1023) * 4 + (j0a >> 10);
    int jb = (j0b & 1023) * 4 + (j0b >> 10);
    int ccl = (lane & 3) * 2;
#pragma unroll
    for (int nn = 0; nn < 16; nn++) {
        int c = blkN * 128 + nn * 8 + ccl;
        int t = c >> 5;
        int b = c & 31;
        float* base = g_xg0 + (size_t)t * GB + b;
        *(float2*)(base + (size_t)ja * 32) = make_float2(acc[nn][0], acc[nn][1]);
        *(float2*)(base + (size_t)jb * 32) = make_float2(acc[nn][2], acc[nn][3]);
    }
}

// ---------------------------------------------------------------------------
__device__ __forceinline__ float sigf(float x) {
    return 1.0f / (1.0f + __expf(-x));
}
__device__ __forceinline__ float tanhfast(float x) {
    return 2.0f / (1.0f + __expf(-2.0f * x)) - 1.0f;
}

// monotonic grid barrier: REDG arrival (no return), acquire-poll by tid 0
__device__ __forceinline__ void grid_sync(unsigned& target) {
    __syncthreads();
    target += GRID_BLOCKS;
    if (threadIdx.x == 0) {
        asm volatile("red.release.gpu.global.add.u32 [%0], %1;"
                     :: "l"(&g_bar_count), "r"(1u) : "memory");
        unsigned v;
        do {
            asm volatile("ld.acquire.gpu.global.u32 %0, [%1];"
                         : "=r"(v) : "l"(&g_bar_count) : "memory");
        } while (v < target);
    }
    __syncthreads();
}

// write h (single fp16) into B-fragment layout
__device__ __forceinline__ void store_h(uint32_t* bdst, int b, int hh, float hn) {
    int k16 = hh >> 4;
    int kc = hh & 15;
    int n8 = b >> 3;
    int nc = b & 7;
    int lane = nc * 4 + ((kc & 7) >> 1);
    int reg = (kc >= 8) ? 1 : 0;
    size_t bidx = (size_t)(((k16 * 4 + n8) * 32 + lane) * 2 + reg) * 2 + (kc & 1);
    ((__half*)bdst)[bidx] = __float2half_rn(hn);
}

// swap register-index bit (1<<R) of v[16] with lane bit (1<<L)
template <int R, int L>
__device__ __forceinline__ void frag_swap(float* v, int lane) {
    bool a = (lane >> L) & 1;
#pragma unroll
    for (int i = 0; i < 16; i++) {
        if (i & (1 << R)) continue;
        int j = i | (1 << R);
        float send = a ? v[i] : v[j];
        float got = __shfl_xor_sync(0xffffffffu, send, 1 << L);
        if (a) v[i] = got; else v[j] = got;
    }
}

// ---------------------------------------------------------------------------
// Persistent LSTM: 128 blocks x 256 threads, monotonic REDG barrier,
// 513 rounds, THREE regions (critical matrix Wh0 gets 2x the SMs):
//   A (bid  0..63): Wh0 @ h0(n), M=64, warps (khalf, tile) split K ->
//     smem combine -> shuffle-transpose -> in-register update -> h0(n+1).
//     MMA on the recurrence chain halved: 256 HMMA/SMSP.
//   B (bid 64..95): Wx1 @ h0(n), M=128, full-K warps (half pinned, half
//     streamed) -> g_part[n&1] for L1 next round.
//   C (bid 96..127): Wh1 @ h1(m-1), m = round-1, M=128, full-K warps ->
//     shuffle-transpose -> in-register L1 update (c1 in registers) -> h1(m).
// ---------------------------------------------------------------------------
__global__ __launch_bounds__(256, 1) void lstm_persist(
    const float* __restrict__ Bias, float* __restrict__ out) {
    extern __shared__ uint32_t sm[];
    uint4* sA = (uint4*)sm;                      // 8192 u4 = 128 KB pinned A
    uint32_t* sB = sm + 32768;                   // 16384 b32 = 64 KB staging
    float* sComb = (float*)(sm + 49152);         // 2048 f32 (region A combine)

    int tid = threadIdx.x;
    int lane = tid & 31;
    int wrp = tid >> 5;
    int bid = blockIdx.x;
    uint32_t sBaddr = smem_u32(sB);
    unsigned target = 0;

    int colb = ((lane >> 2) & 3) * 8 + (lane & 3) * 2;   // update column base

    if (bid < 64) {
        // ========================= REGION A : Wh0 ==========================
        int blk = bid;
        int tile = wrp & 3;
        int kh = wrp >> 2;
        // pin Wh0 slice: mat0 tiles blk*4..+3
        {
            const uint4* Apin = (const uint4*)g_Ahi + (size_t)(blk * 4) * NK16 * 32;
            for (int i = tid; i < 8192; i += 256) sA[i] = Apin[i];
        }
        float bgr[4][2];
        float creg[4];
        if (kh == 0) {
#pragma unroll
            for (int g = 0; g < 4; g++)
#pragma unroll
                for (int h2 = 0; h2 < 2; h2++) {
                    int hh_l = tile * 4 + (lane >> 4) + 2 * h2;
                    bgr[g][h2] = Bias[g * 1024 + blk * 16 + hh_l];
                }
            // prologue: h0(0) = cell(c=0, xg0[0] + bias)
            const float* xg = g_xg0 + (size_t)(blk * 64) * 32;
#pragma unroll
            for (int h2 = 0; h2 < 2; h2++) {
                int hh_l = tile * 4 + (lane >> 4) + 2 * h2;
#pragma unroll
                for (int cp = 0; cp < 2; cp++) {
                    int col = colb + cp;
                    float w = xg[(4 * hh_l + 1) * 32 + col] + bgr[1][h2];
                    float i_ = xg[(4 * hh_l + 2) * 32 + col] + bgr[2][h2];
                    float o = xg[(4 * hh_l + 3) * 32 + col] + bgr[3][h2];
                    float cn = sigf(w) * tanhfast(i_);
                    float hn = tanhfast(cn) * sigf(o);
                    creg[h2 * 2 + cp] = cn;
                    store_h(g_B0[0], col, blk * 16 + hh_l, hn);
                }
            }
        }

        for (int n = 0; n < NT; n++) {
            float2 xr2[8];
            if (kh == 0 && n < NT - 1) {
                const float* xg = g_xg0 + (size_t)(n + 1) * GB +
                                  (size_t)(blk * 64) * 32;
#pragma unroll
                for (int g = 0; g < 4; g++)
#pragma unroll
                    for (int h2 = 0; h2 < 2; h2++) {
                        int hh_l = tile * 4 + (lane >> 4) + 2 * h2;
                        xr2[g * 2 + h2] =
                            *(const float2*)(xg + (size_t)(4 * hh_l + g) * 32 + colb);
                    }
            }
            grid_sync(target);
            if (n >= NT - 1) continue;           // no h0(512) needed
            // stage h0(n)
            {
                const uint32_t* src = g_B0[n & 1];
#pragma unroll
                for (int i = 0; i < 16; i++) {
                    int u = tid + i * 256;
                    cp16(sBaddr + u * 16, src + u * 4);
                }
                CP_COMMIT();
                CP_WAIT0();
            }
            __syncthreads();

            float accf[16];
#pragma unroll
            for (int i = 0; i < 16; i++) accf[i] = 0.0f;
#pragma unroll 8
            for (int kk = 0; kk < 32; kk++) {
                int k16 = kh * 32 + kk;
                uint4 a = sA[(tile * 64 + k16) * 32 + lane];
#pragma unroll
                for (int nt = 0; nt < 4; nt++) {
                    int bix = (k16 * 4 + nt) * 64 + lane * 2;
                    mma_f16(&accf[nt * 4], a, sB[bix], sB[bix + 1]);
                }
            }
            // combine K-halves via smem
            if (kh == 1) {
                float4* dst = (float4*)&sComb[(tile * 32 + lane) * 16];
#pragma unroll
                for (int q = 0; q < 4; q++)
                    dst[q] = make_float4(accf[q * 4], accf[q * 4 + 1],
                                         accf[q * 4 + 2], accf[q * 4 + 3]);
            }
            __syncthreads();
            if (kh == 0) {
                const float4* src4 = (const float4*)&sComb[(tile * 32 + lane) * 16];
#pragma unroll
                for (int q = 0; q < 4; q++) {
                    float4 v = src4[q];
                    accf[q * 4] += v.x; accf[q * 4 + 1] += v.y;
                    accf[q * 4 + 2] += v.z; accf[q * 4 + 3] += v.w;
                }
                frag_swap<2, 2>(accf, lane);
                frag_swap<3, 3>(accf, lane);
#pragma unroll
                for (int q = 0; q < 4; q++) {
                    int h2 = q >> 1, cp = q & 1;
                    int hh_l = tile * 4 + (lane >> 4) + 2 * h2;
                    int col = colb + cp;
                    float xf = cp ? xr2[0 * 2 + h2].y : xr2[0 * 2 + h2].x;
                    float xw = cp ? xr2[1 * 2 + h2].y : xr2[1 * 2 + h2].x;
                    float xi = cp ? xr2[2 * 2 + h2].y : xr2[2 * 2 + h2].x;
                    float xo = cp ? xr2[3 * 2 + h2].y : xr2[3 * 2 + h2].x;
                    float f = accf[0 + q] + xf + bgr[0][h2];
                    float w = accf[4 + q] + xw + bgr[1][h2];
                    float i_ = accf[8 + q] + xi + bgr[2][h2];
                    float o = accf[12 + q] + xo + bgr[3][h2];
                    float cv = creg[q];
                    float cn = cv * sigf(f) + sigf(w) * tanhfast(i_);
                    float hn = tanhfast(cn) * sigf(o);
                    creg[q] = cn;
                    store_h(g_B0[(n + 1) & 1], col, blk * 16 + hh_l, hn);
                }
            }
        }
        grid_sync(target);                       // final round (s = NT)
    } else if (bid < 96) {
        // ========================= REGION B : Wx1 ==========================
        int blk2 = bid - 64;
        // pin first half of Wx1 slice (tiles blk2*8..+3); warps 4-7 stream
        {
            const uint4* Apin = (const uint4*)g_Ahi + 2 * MAT_U4 +
                (size_t)(blk2 * 8) * NK16 * 32;
            for (int i = tid; i < 8192; i += 256) sA[i] = Apin[i];
        }
        const uint4* A2s = (const uint4*)g_Ahi + 2 * MAT_U4 +
            (size_t)(blk2 * 8 + wrp) * NK16 * 32;

        for (int n = 0; n < NT; n++) {
            grid_sync(target);
            // stage h0(n)
            {
                const uint32_t* src = g_B0[n & 1];
#pragma unroll
                for (int i = 0; i < 16; i++) {
                    int u = tid + i * 256;
                    cp16(sBaddr + u * 16, src + u * 4);
                }
                CP_COMMIT();
                CP_WAIT0();
            }
            __syncthreads();

            float accf[16];
#pragma unroll
            for (int i = 0; i < 16; i++) accf[i] = 0.0f;
#pragma unroll 8
            for (int k16 = 0; k16 < NK16; k16++) {
                uint4 a = (wrp < 4) ? sA[(wrp * 64 + k16) * 32 + lane]
                                    : A2s[k16 * 32 + lane];
#pragma unroll
                for (int nt = 0; nt < 4; nt++) {
                    int bix = (k16 * 4 + nt) * 64 + lane * 2;
                    mma_f16(&accf[nt * 4], a, sB[bix], sB[bix + 1]);
                }
            }
            int r0 = wrp * 16 + (lane >> 2);
            int cc = (lane & 3) * 2;
            float* gp = g_part[n & 1] + (size_t)(blk2 * 128) * 32;
#pragma unroll
            for (int nt = 0; nt < 4; nt++) {
                *(float2*)(gp + (size_t)r0 * 32 + nt * 8 + cc) =
                    make_float2(accf[nt * 4 + 0], accf[nt * 4 + 1]);
                *(float2*)(gp + (size_t)(r0 + 8) * 32 + nt * 8 + cc) =
                    make_float2(accf[nt * 4 + 2], accf[nt * 4 + 3]);
            }
        }
        grid_sync(target);                       // final round
    } else {
        // ========================= REGION C : Wh1 + L1 update ==============
        int blk2 = bid - 96;
        {
            const uint4* Apin = (const uint4*)g_Ahi + 1 * MAT_U4 +
                (size_t)(blk2 * 8) * NK16 * 32;
            for (int i = tid; i < 8192; i += 256) sA[i] = Apin[i];
        }
        const uint4* A1s = (const uint4*)g_Ahi + 1 * MAT_U4 +
            (size_t)(blk2 * 8 + wrp) * NK16 * 32;

        float bgr[4][2];
        float creg[4] = {0.0f, 0.0f, 0.0f, 0.0f};
#pragma unroll
        for (int g = 0; g < 4; g++)
#pragma unroll
            for (int h2 = 0; h2 < 2; h2++) {
                int hh_l = wrp * 4 + (lane >> 4) + 2 * h2;
                bgr[g][h2] = Bias[4096 + g * 1024 + blk2 * 32 + hh_l];
            }

        for (int s = 0; s <= NT; s++) {
            grid_sync(target);
            if (s < 1) continue;
            int m = s - 1;

            float accf[16];
#pragma unroll
            for (int i = 0; i < 16; i++) accf[i] = 0.0f;

            if (m >= 1) {
                // stage h1(m-1)
                const uint32_t* src = g_B1[(m - 1) & 1];
#pragma unroll
                for (int i = 0; i < 16; i++) {
                    int u = tid + i * 256;
                    cp16(sBaddr + u * 16, src + u * 4);
                }
                CP_COMMIT();
            }
            // load this round's partial gates (written by region B last round)
            float2 gpr2[8];
            {
                const float* gp = g_part[m & 1] + (size_t)(blk2 * 128) * 32;
#pragma unroll
                for (int g = 0; g < 4; g++)
#pragma unroll
                    for (int h2 = 0; h2 < 2; h2++) {
                        int hh_l = wrp * 4 + (lane >> 4) + 2 * h2;
                        gpr2[g * 2 + h2] =
                            *(const float2*)(gp + (size_t)(4 * hh_l + g) * 32 + colb);
                    }
            }
            if (m >= 1) {
                CP_WAIT0();
                __syncthreads();
#pragma unroll 8
                for (int k16 = 0; k16 < NK16; k16++) {
                    uint4 a = (wrp < 4) ? sA[(wrp * 64 + k16) * 32 + lane]
                                        : A1s[k16 * 32 + lane];
#pragma unroll
                    for (int nt = 0; nt < 4; nt++) {
                        int bix = (k16 * 4 + nt) * 64 + lane * 2;
                        mma_f16(&accf[nt * 4], a, sB[bix], sB[bix + 1]);
                    }
                }
            }
            frag_swap<2, 2>(accf, lane);
            frag_swap<3, 3>(accf, lane);
            // in-register L1 cell update -> h1(m)
#pragma unroll
            for (int q = 0; q < 4; q++) {
                int h2 = q >> 1, cp = q & 1;
                int hh_l = wrp * 4 + (lane >> 4) + 2 * h2;
                int col = colb + cp;
                float pf = cp ? gpr2[0 * 2 + h2].y : gpr2[0 * 2 + h2].x;
                float pw = cp ? gpr2[1 * 2 + h2].y : gpr2[1 * 2 + h2].x;
                float pi = cp ? gpr2[2 * 2 + h2].y : gpr2[2 * 2 + h2].x;
                float po = cp ? gpr2[3 * 2 + h2].y : gpr2[3 * 2 + h2].x;
                float f = accf[0 + q] + pf + bgr[0][h2];
                float w = accf[4 + q] + pw + bgr[1][h2];
                float i_ = accf[8 + q] + pi + bgr[2][h2];
                float o = accf[12 + q] + po + bgr[3][h2];
                float cv = creg[q];
                float cn = cv * sigf(f) + sigf(w) * tanhfast(i_);
                float hn = tanhfast(cn) * sigf(o);
                creg[q] = cn;
                store_h(g_B1[m & 1], col, blk2 * 32 + hh_l, hn);
                if (m == NT - 1) out[col * 1024 + blk2 * 32 + hh_l] = hn;
            }
        }
    }
}

// ---------------------------------------------------------------------------
extern "C" void kernel_launch(void* const* d_in, const int* in_sizes, int n_in,
                              void* d_out, int out_size) {
    const float* seq  = (const float*)d_in[0];  // (32, 512, 1024)
    const float* Wh   = (const float*)d_in[1];  // (2, 4, 1024, 1024)
    const float* Wx   = (const float*)d_in[2];  // (2, 4, 1024, 1024)
    const float* Bias = (const float*)d_in[3];  // (2, 4, 1024)
    float* out = (float*)d_out;                 // (32, 1024)

    cudaFuncSetAttribute(lstm_persist,
                         cudaFuncAttributeMaxDynamicSharedMemorySize, SMEM_BYTES);
    cudaFuncSetAttribute(pregemm_mma,
                         cudaFuncAttributeMaxDynamicSharedMemorySize, PRE_SMEM);

    init_state<<<64, 256>>>();
    prep_weights<<<4 * 4096 * 1024 / 256, 256>>>(Wh, Wx);
    prep_seq<<<NB * NT * NI / 256, 256>>>(seq);
    pregemm_mma<<<dim3(32, 128), 256, PRE_SMEM>>>();
    lstm_persist<<<GRID_BLOCKS, 256, SMEM_BYTES>>>(Bias, out);
}

// round 16
// speedup vs baseline: 1.2033x; 1.0947x over previous
#include <cuda_runtime.h>
#include <cuda_fp16.h>
#include <math.h>
#include <stdint.h>

#define NB 32
#define NT 512
#define NI 1024
#define NH 1024
#define NG 4096
#define GB (NG*NB)              // gate elems per step, layout [t][j'][b]
#define LOFF (4*NH*NI)
#define GRID_BLOCKS 128
#define NK16 64                 // K=1024 in 64 chunks of 16
#define B_B32 16384             // one B vector in b32: 64*4*32*2 (fp16 single)
#define MAT_U4 524288           // uint4 stride per A matrix (4096x1024 fp16)
#define MAT_U32 2097152         // uint32 stride per A matrix
// smem: sA 8192 u4 (128K) + sB 16384 b32 (64K) + sTile 2048 f (8K) + sC 512 f (2K)
#define SMEM_BYTES (131072 + 65536 + 8192 + 2048)
#define PRE_SMEM 32768

// ---------------- device scratch -------------------------------------------
__device__ __align__(256) float g_xg0[(size_t)(NT + 1) * GB]; // [t][j'][b]
// A fragments fp16 in m16n8k16 A layout.
// mats 0-2 (Wh0, Wh1, Wx1): interleaved rows j'=hh*4+g, [blk64][tile4][k16][lane]
// mat 3 (Wx0, pregemm): original rows, [blk32][warp8][k16][lane]
__device__ __align__(128) __half g_Ahi[(size_t)4 * 4096 * 1024];
__device__ __align__(128) __half g_Alo[(size_t)4096 * 1024];   // mat3 only
// seq B-fragments (hi only)
__device__ __align__(128) __half g_Sh[(size_t)64 * 2048 * 128];
// h B-fragments (single fp16), double-buffered by parity
__device__ __align__(128) uint32_t g_B0[2][B_B32];
__device__ __align__(128) uint32_t g_B1[2][B_B32];
// Wx1 @ h0 partial gate sums, double-buffered by parity: [p][j'][b]
__device__ __align__(256) float g_part[2][NG * NB];
__device__ unsigned g_bar_count;

// ---------------------------------------------------------------------------
__global__ void init_state() {
    int i = blockIdx.x * blockDim.x + threadIdx.x;
    int n = gridDim.x * blockDim.x;
    for (int k = i; k < B_B32; k += n) {
        g_B0[0][k] = 0u; g_B0[1][k] = 0u;
        g_B1[0][k] = 0u; g_B1[1][k] = 0u;
    }
    if (i == 0) g_bar_count = 0;
}

// ---------------------------------------------------------------------------
// Weights -> fp16 A-fragments, COALESCED: one thread per output uint32.
// Writer (T, k16, lane, reg) -> row16 = (lane>>2)|((reg&1)<<3),
//   kc0 = 2*(lane&3) + 8*(reg>>1); reads float2 src[j][k16*16+kc0 .. +1].
// mats 0-2: row j' = T*16+row16 interleaved (j = g*1024+hh, j' = hh*4+g).
// mat 3 (Wx0): original rows; also writes g_Alo (hi/lo split for pregemm).
// ---------------------------------------------------------------------------
__global__ __launch_bounds__(256) void prep_weights(const float* __restrict__ Wh,
                                                    const float* __restrict__ Wx) {
    size_t i = (size_t)blockIdx.x * 256 + threadIdx.x;   // 0 .. 4*2M-1
    int r = (int)(i >> 21);
    int rem = (int)(i & (MAT_U32 - 1));
    int reg = rem & 3;
    int lane = (rem >> 2) & 31;
    int k16 = (rem >> 7) & 63;
    int T = rem >> 13;                 // 0..255
    int row16 = (lane >> 2) | ((reg & 1) << 3);
    int kc0 = 2 * (lane & 3) + ((reg >> 1) << 3);
    int k = k16 * 16 + kc0;

    int j;                              // source row
    if (r == 3) {
        j = T * 16 + row16;
    } else {
        int jp = T * 16 + row16;        // interleaved row j' = hh*4+g
        j = (jp & 3) * 1024 + (jp >> 2);
    }
    const float* src = (r == 0) ? Wh : (r == 1) ? (Wh + LOFF)
                     : (r == 2) ? (Wx + LOFF) : Wx;
    float2 w = *(const float2*)(src + (size_t)j * NI + k);

    __half h0 = __float2half_rn(w.x);
    __half h1 = __float2half_rn(w.y);
    ((__half2*)g_Ahi)[i] = __halves2half2(h0, h1);
    if (r == 3) {
        __half l0 = __float2half_rn(w.x - __half2float(h0));
        __half l1 = __float2half_rn(w.y - __half2float(h1));
        ((__half2*)g_Alo)[rem] = __halves2half2(l0, l1);
    }
}

// ---------------------------------------------------------------------------
// seq -> fp16 B-fragments, COALESCED: one thread per output uint32.
// idx u32 = ((k16*2048 + n8)*32 + lane)*2 + reg;
//   nc = lane>>2, kc0 = 2*(lane&3) + 8*reg, c = n8*8+nc, t = c>>5, b = c&31.
// ---------------------------------------------------------------------------
__global__ __launch_bounds__(256) void prep_seq(const float* __restrict__ seq) {
    size_t i = (size_t)blockIdx.x * 256 + threadIdx.x;   // 0 .. 8M-1
    int reg = (int)(i & 1);
    int lane = (int)(i >> 1) & 31;
    int n8 = (int)(i >> 6) & 2047;
    int k16 = (int)(i >> 17);
    int nc = lane >> 2;
    int kc0 = 2 * (lane & 3) + (reg << 3);
    int c = n8 * 8 + nc;
    int t = c >> 5;
    int b = c & 31;
    int k = k16 * 16 + kc0;
    float2 v = *(const float2*)(seq + ((size_t)b * NT + t) * NI + k);
    ((__half2*)g_Sh)[i] = __halves2half2(__float2half_rn(v.x),
                                         __float2half_rn(v.y));
}

// ---------------------------------------------------------------------------
__device__ __forceinline__ void mma_f16(float* d, const uint4& a,
                                        uint32_t b0, uint32_t b1) {
    asm volatile(
        "mma.sync.aligned.m16n8k16.row.col.f32.f16.f16.f32 "
        "{%0,%1,%2,%3},{%4,%5,%6,%7},{%8,%9},{%0,%1,%2,%3};"
        : "+f"(d[0]), "+f"(d[1]), "+f"(d[2]), "+f"(d[3])
        : "r"(a.x), "r"(a.y), "r"(a.z), "r"(a.w), "r"(b0), "r"(b1));
}
__device__ __forceinline__ uint32_t smem_u32(const void* p) {
    uint32_t a;
    asm("{ .reg .u64 t; cvta.to.shared.u64 t, %1; cvt.u32.u64 %0, t; }"
        : "=r"(a) : "l"(p));
    return a;
}
__device__ __forceinline__ void cp16(uint32_t dst, const void* src) {
    asm volatile("cp.async.cg.shared.global [%0], [%1], 16;"
                 :: "r"(dst), "l"(src));
}
#define CP_COMMIT() asm volatile("cp.async.commit_group;")
#define CP_WAIT0()  asm volatile("cp.async.wait_group 0;")

// ---------------------------------------------------------------------------
// Pregemm: xg0[t][j'][b] = Wx0 @ x, fp16 2-pass (A hi/lo, B single fp16).
// ---------------------------------------------------------------------------
__global__ __launch_bounds__(256) void pregemm_mma() {
    extern __shared__ uint32_t sm[];
    uint32_t* sBh = sm;

    int tid = threadIdx.x;
    int lane = tid & 31;
    int wrp = tid >> 5;
    int blkM = blockIdx.x;
    int blkN = blockIdx.y;

    const uint4* Ah_w = (const uint4*)g_Ahi + 3 * MAT_U4 +
        (size_t)(blkM * 8 + wrp) * NK16 * 32;
    const uint4* Al_w = (const uint4*)g_Alo +
        (size_t)(blkM * 8 + wrp) * NK16 * 32;
    const uint4* gSh = (const uint4*)g_Sh;

    float acc[16][4];
#pragma unroll
    for (int nn = 0; nn < 16; nn++)
#pragma unroll
        for (int q = 0; q < 4; q++) acc[nn][q] = 0.0f;

    for (int kc8 = 0; kc8 < 8; kc8++) {
#pragma unroll
        for (int it = 0; it < 8; it++) {
            int flat = it * 256 + tid;
            int kk = flat >> 8;
            int rem = flat & 255;
            int nn = rem >> 4;
            int q = rem & 15;
            size_t srcu4 = ((size_t)(kc8 * 8 + kk) * 2048 + blkN * 16 + nn) * 16 + q;
            ((uint4*)sBh)[flat] = gSh[srcu4];
        }
        __syncthreads();
#pragma unroll 2
        for (int kk = 0; kk < 8; kk++) {
            int k16 = kc8 * 8 + kk;
            uint4 ah = Ah_w[k16 * 32 + lane];
            uint4 al = Al_w[k16 * 32 + lane];
#pragma unroll
            for (int nn = 0; nn < 16; nn++) {
                int bix = ((kk * 16 + nn) * 32 + lane) * 2;
                mma_f16(acc[nn], ah, sBh[bix], sBh[bix + 1]);
            }
#pragma unroll
            for (int nn = 0; nn < 16; nn++) {
                int bix = ((kk * 16 + nn) * 32 + lane) * 2;
                mma_f16(acc[nn], al, sBh[bix], sBh[bix + 1]);
            }
        }
        __syncthreads();
    }
    int j0a = blkM * 128 + wrp * 16 + (lane >> 2);
    int j0b = j0a + 8;
    int ja = (j0a & 1023) * 4 + (j0a >> 10);
    int jb = (j0b & 1023) * 4 + (j0b >> 10);
    int ccl = (lane & 3) * 2;
#pragma unroll
    for (int nn = 0; nn < 16; nn++) {
        int c = blkN * 128 + nn * 8 + ccl;
        int t = c >> 5;
        int b = c & 31;
        float* base = g_xg0 + (size_t)t * GB + b;
        *(float2*)(base + (size_t)ja * 32) = make_float2(acc[nn][0], acc[nn][1]);
        *(float2*)(base + (size_t)jb * 32) = make_float2(acc[nn][2], acc[nn][3]);
    }
}

// ---------------------------------------------------------------------------
__device__ __forceinline__ float sigf(float x) {
    return 1.0f / (1.0f + __expf(-x));
}
__device__ __forceinline__ float tanhfast(float x) {
    return 2.0f / (1.0f + __expf(-2.0f * x)) - 1.0f;
}

// monotonic grid barrier: REDG arrival (no return), acquire-poll by tid 0
__device__ __forceinline__ void grid_sync(unsigned& target) {
    __syncthreads();
    target += GRID_BLOCKS;
    if (threadIdx.x == 0) {
        asm volatile("red.release.gpu.global.add.u32 [%0], %1;"
                     :: "l"(&g_bar_count), "r"(1u) : "memory");
        unsigned v;
        do {
            asm volatile("ld.acquire.gpu.global.u32 %0, [%1];"
                         : "=r"(v) : "l"(&g_bar_count) : "memory");
        } while (v < target);
    }
    __syncthreads();
}

// write h (single fp16) into B-fragment layout
__device__ __forceinline__ void store_h(uint32_t* bdst, int b, int hh, float hn) {
    int k16 = hh >> 4;
    int kc = hh & 15;
    int n8 = b >> 3;
    int nc = b & 7;
    int lane = nc * 4 + ((kc & 7) >> 1);
    int reg = (kc >= 8) ? 1 : 0;
    size_t bidx = (size_t)(((k16 * 4 + n8) * 32 + lane) * 2 + reg) * 2 + (kc & 1);
    ((__half*)bdst)[bidx] = __float2half_rn(hn);
}

// swap register-index bit (1<<R) of v[16] with lane bit (1<<L)
template <int R, int L>
__device__ __forceinline__ void frag_swap(float* v, int lane) {
    bool a = (lane >> L) & 1;
#pragma unroll
    for (int i = 0; i < 16; i++) {
        if (i & (1 << R)) continue;
        int j = i | (1 << R);
        float send = a ? v[i] : v[j];
        float got = __shfl_xor_sync(0xffffffffu, send, 1 << L);
        if (a) v[i] = got; else v[j] = got;
    }
}

// ---------------------------------------------------------------------------
// Persistent LSTM (R12 structure, unchanged): 128 blocks x 256 threads,
// monotonic REDG barrier, 513 rounds, L1 lags L0 by one round.
//   L0 (bid 0..63): round n: stage h0(n) once; warps 0-3 Wh0 (pinned) @ h0 ->
//     shuffle-transpose -> in-register cell update (c in registers);
//     warps 4-7 Wx1 (streamed) @ h0 -> g_part.  xr prefetched PRE-barrier.
//   L1 (bid 64..127): round s, m=s-1: stage h1(m-1); Wh1 (pinned) @ h1 ->
//     sTile combine; gates = sTile + g_part[m&1] + bias -> h1(m).
// ---------------------------------------------------------------------------
__global__ __launch_bounds__(256, 1) void lstm_persist(
    const float* __restrict__ Bias, float* __restrict__ out) {
    extern __shared__ uint32_t sm[];
    uint4* sA = (uint4*)sm;                      // 8192 u4 = 128 KB pinned A
    uint32_t* sB = sm + 32768;                   // 16384 b32 = 64 KB
    float* sTile = (float*)(sm + 49152);         // 2048 f32 (L1 only)
    float* sC = sTile + 2048;                    // 512 f32  (L1 only)

    int tid = threadIdx.x;
    int lane = tid & 31;
    int wrp = tid >> 5;
    int bid = blockIdx.x;
    int region = (bid < 64) ? 0 : 1;
    int blk = bid & 63;
    uint32_t sBaddr = smem_u32(sB);

    // preload pinned A slice (mat0=Wh0 for L0, mat1=Wh1 for L1), 8192 uint4
    {
        const uint4* Apin = (const uint4*)g_Ahi +
            (size_t)region * MAT_U4 + (size_t)(blk * 4) * NK16 * 32;
        for (int i = tid; i < 8192; i += 256) sA[i] = Apin[i];
    }

    int tile = wrp & 3;
    int mat = wrp >> 2;   // L0: 0=Wh0 (pinned), 1=Wx1 (streamed); L1: khalf

    const uint4* A2 = (const uint4*)g_Ahi + 2 * MAT_U4 +
        (size_t)(blk * 4 + tile) * NK16 * 32;    // Wx1 slice (L0 warps 4-7)

    unsigned target = 0;

    if (region == 0) {
        // ------------------------------ LAYER 0 ------------------------------
        int colb = ((lane >> 2) & 3) * 8 + (lane & 3) * 2;
        float bgr[4][2];
        float creg[4];
        if (mat == 0) {
#pragma unroll
            for (int g = 0; g < 4; g++)
#pragma unroll
                for (int h2 = 0; h2 < 2; h2++) {
                    int hh_l = tile * 4 + (lane >> 4) + 2 * h2;
                    bgr[g][h2] = Bias[g * 1024 + blk * 16 + hh_l];
                }
            // prologue: h0(0) = cell(c=0, xg0[0] + bias) -> g_B0[0]
            const float* xg = g_xg0 + (size_t)(blk * 64) * 32;
#pragma unroll
            for (int h2 = 0; h2 < 2; h2++) {
                int hh_l = tile * 4 + (lane >> 4) + 2 * h2;
#pragma unroll
                for (int cp = 0; cp < 2; cp++) {
                    int col = colb + cp;
                    float w = xg[(4 * hh_l + 1) * 32 + col] + bgr[1][h2];
                    float i_ = xg[(4 * hh_l + 2) * 32 + col] + bgr[2][h2];
                    float o = xg[(4 * hh_l + 3) * 32 + col] + bgr[3][h2];
                    float cn = sigf(w) * tanhfast(i_);
                    float hn = tanhfast(cn) * sigf(o);
                    creg[h2 * 2 + cp] = cn;
                    store_h(g_B0[0], col, blk * 16 + hh_l, hn);
                }
            }
        }

        for (int n = 0; n < NT; n++) {
            // PRE-barrier: prefetch next-step input gates (static data)
            float2 xr2[8];
            if (mat == 0 && n < NT - 1) {
                const float* xg = g_xg0 + (size_t)(n + 1) * GB +
                                  (size_t)(blk * 64) * 32;
#pragma unroll
                for (int g = 0; g < 4; g++)
#pragma unroll
                    for (int h2 = 0; h2 < 2; h2++) {
                        int hh_l = tile * 4 + (lane >> 4) + 2 * h2;
                        xr2[g * 2 + h2] =
                            *(const float2*)(xg + (size_t)(4 * hh_l + g) * 32 + colb);
                    }
            }
            grid_sync(target);
            int p = n & 1;
            // stage h0(n) fragments (64 KB)
            {
                const uint32_t* src = g_B0[p];
#pragma unroll
                for (int i = 0; i < 16; i++) {
                    int u = tid + i * 256;
                    cp16(sBaddr + u * 16, src + u * 4);
                }
                CP_COMMIT();
                CP_WAIT0();
            }
            __syncthreads();

            float accf[16];
#pragma unroll
            for (int i = 0; i < 16; i++) accf[i] = 0.0f;

            if (mat == 0) {
                if (n < NT - 1) {
#pragma unroll 8
                    for (int k16 = 0; k16 < NK16; k16++) {
                        uint4 a = sA[(tile * 64 + k16) * 32 + lane];
#pragma unroll
                        for (int nt = 0; nt < 4; nt++) {
                            int bix = (k16 * 4 + nt) * 64 + lane * 2;
                            mma_f16(&accf[nt * 4], a, sB[bix], sB[bix + 1]);
                        }
                    }
                    // shuffle-transpose: reg bits 2,3 (nt) <-> lane bits 2,3 (g)
                    frag_swap<2, 2>(accf, lane);
                    frag_swap<3, 3>(accf, lane);
                    // in-register cell update -> h0(n+1)
#pragma unroll
                    for (int q = 0; q < 4; q++) {
                        int h2 = q >> 1, cp = q & 1;
                        int hh_l = tile * 4 + (lane >> 4) + 2 * h2;
                        int col = colb + cp;
                        float xf = cp ? xr2[0 * 2 + h2].y : xr2[0 * 2 + h2].x;
                        float xw = cp ? xr2[1 * 2 + h2].y : xr2[1 * 2 + h2].x;
                        float xi = cp ? xr2[2 * 2 + h2].y : xr2[2 * 2 + h2].x;
                        float xo = cp ? xr2[3 * 2 + h2].y : xr2[3 * 2 + h2].x;
                        float f = accf[0 + q] + xf + bgr[0][h2];
                        float w = accf[4 + q] + xw + bgr[1][h2];
                        float i_ = accf[8 + q] + xi + bgr[2][h2];
                        float o = accf[12 + q] + xo + bgr[3][h2];
                        float cv = creg[q];
                        float cn = cv * sigf(f) + sigf(w) * tanhfast(i_);
                        float hn = tanhfast(cn) * sigf(o);
                        creg[q] = cn;
                        store_h(g_B0[(n + 1) & 1], col, blk * 16 + hh_l, hn);
                    }
                }
            } else {
                // Wx1 @ h0(n) -> partial gates for L1 next round
#pragma unroll 8
                for (int k16 = 0; k16 < NK16; k16++) {
                    uint4 a = A2[k16 * 32 + lane];
#pragma unroll
                    for (int nt = 0; nt < 4; nt++) {
                        int bix = (k16 * 4 + nt) * 64 + lane * 2;
                        mma_f16(&accf[nt * 4], a, sB[bix], sB[bix + 1]);
                    }
                }
                int r0 = tile * 16 + (lane >> 2);
                int cc = (lane & 3) * 2;
                float* gp = g_part[p] + (size_t)(blk * 64) * 32;
#pragma unroll
                for (int nt = 0; nt < 4; nt++) {
                    *(float2*)(gp + (size_t)r0 * 32 + nt * 8 + cc) =
                        make_float2(accf[nt * 4 + 0], accf[nt * 4 + 1]);
                    *(float2*)(gp + (size_t)(r0 + 8) * 32 + nt * 8 + cc) =
                        make_float2(accf[nt * 4 + 2], accf[nt * 4 + 3]);
                }
            }
            __syncthreads();
        }
        grid_sync(target);                       // round s = NT (L1 finishes)
    } else {
        // ------------------------------ LAYER 1 ------------------------------
        float bf[2], bw[2], bi_[2], bo[2];
#pragma unroll
        for (int i = 0; i < 2; i++) {
            int hh = blk * 16 + ((tid + i * 256) >> 5);
            bf[i] = Bias[4096 + hh];        bw[i] = Bias[4096 + 1024 + hh];
            bi_[i] = Bias[4096 + 2048 + hh]; bo[i] = Bias[4096 + 3072 + hh];
        }
#pragma unroll
        for (int i = 0; i < 2; i++) sC[tid + i * 256] = 0.0f;
        __syncthreads();

        for (int s = 0; s <= NT; s++) {
            grid_sync(target);
            if (s < 1) continue;
            int m = s - 1;
            if (m >= 1) {
                // stage h1(m-1) (64 KB)
                {
                    const uint32_t* src = g_B1[(m - 1) & 1];
#pragma unroll
                    for (int i = 0; i < 16; i++) {
                        int u = tid + i * 256;
                        cp16(sBaddr + u * 16, src + u * 4);
                    }
                    CP_COMMIT();
                    CP_WAIT0();
                }
                __syncthreads();

                float accf[16];
#pragma unroll
                for (int i = 0; i < 16; i++) accf[i] = 0.0f;
#pragma unroll 8
                for (int kk = 0; kk < 32; kk++) {
                    int k16 = mat * 32 + kk;
                    uint4 a = sA[(tile * 64 + k16) * 32 + lane];
#pragma unroll
                    for (int nt = 0; nt < 4; nt++) {
                        int bix = (k16 * 4 + nt) * 64 + lane * 2;
                        mma_f16(&accf[nt * 4], a, sB[bix], sB[bix + 1]);
                    }
                }
                // combine K-halves in sTile
                int r0 = tile * 16 + (lane >> 2);
                int cc = (lane & 3) * 2;
                if (mat == 0) {
#pragma unroll
                    for (int nt = 0; nt < 4; nt++) {
                        *(float2*)&sTile[r0 * 32 + nt * 8 + cc] =
                            make_float2(accf[nt * 4 + 0], accf[nt * 4 + 1]);
                        *(float2*)&sTile[(r0 + 8) * 32 + nt * 8 + cc] =
                            make_float2(accf[nt * 4 + 2], accf[nt * 4 + 3]);
                    }
                }
                __syncthreads();
                if (mat == 1) {
#pragma unroll
                    for (int nt = 0; nt < 4; nt++) {
                        float2* p0 = (float2*)&sTile[r0 * 32 + nt * 8 + cc];
                        float2* p1 = (float2*)&sTile[(r0 + 8) * 32 + nt * 8 + cc];
                        float2 v0 = *p0, v1 = *p1;
                        v0.x += accf[nt * 4 + 0]; v0.y += accf[nt * 4 + 1];
                        v1.x += accf[nt * 4 + 2]; v1.y += accf[nt * 4 + 3];
                        *p0 = v0; *p1 = v1;
                    }
                }
                __syncthreads();
            } else {
                // m == 0: h1(-1) = 0, recurrent term vanishes
                for (int i = tid; i < 2048; i += 256) sTile[i] = 0.0f;
                __syncthreads();
            }
            // fused cell update: gates = sTile + partial(m) + bias -> h1(m)
            const float* gp = g_part[m & 1] + (size_t)(blk * 64) * 32;
#pragma unroll
            for (int i = 0; i < 2; i++) {
                int q = tid + i * 256;
                int hh_l = q >> 5, b = q & 31, br = hh_l * 4;
                float f = sTile[br * 32 + b] + gp[br * 32 + b] + bf[i];
                float w = sTile[(br + 1) * 32 + b] + gp[(br + 1) * 32 + b] + bw[i];
                float i_ = sTile[(br + 2) * 32 + b] + gp[(br + 2) * 32 + b] + bi_[i];
                float o = sTile[(br + 3) * 32 + b] + gp[(br + 3) * 32 + b] + bo[i];
                float cv = sC[q];
                float cn = cv * sigf(f) + sigf(w) * tanhfast(i_);
                float hn = tanhfast(cn) * sigf(o);
                sC[q] = cn;
                store_h(g_B1[m & 1], b, blk * 16 + hh_l, hn);
                if (m == NT - 1) out[b * 1024 + blk * 16 + hh_l] = hn;
            }
            __syncthreads();
        }
    }
}

// ---------------------------------------------------------------------------
extern "C" void kernel_launch(void* const* d_in, const int* in_sizes, int n_in,
                              void* d_out, int out_size) {
    const float* seq  = (const float*)d_in[0];  // (32, 512, 1024)
    const float* Wh   = (const float*)d_in[1];  // (2, 4, 1024, 1024)
    const float* Wx   = (const float*)d_in[2];  // (2, 4, 1024, 1024)
    const float* Bias = (const float*)d_in[3];  // (2, 4, 1024)
    float* out = (float*)d_out;                 // (32, 1024)

    cudaFuncSetAttribute(lstm_persist,
                         cudaFuncAttributeMaxDynamicSharedMemorySize, SMEM_BYTES);
    cudaFuncSetAttribute(pregemm_mma,
                         cudaFuncAttributeMaxDynamicSharedMemorySize, PRE_SMEM);

    init_state<<<64, 256>>>();
    prep_weights<<<4 * MAT_U32 / 256, 256>>>(Wh, Wx);
    prep_seq<<<8 * 1024 * 1024 / 256, 256>>>(seq);
    pregemm_mma<<<dim3(32, 128), 256, PRE_SMEM>>>();
    lstm_persist<<<GRID_BLOCKS, 256, SMEM_BYTES>>>(Bias, out);
}

// round 17
// speedup vs baseline: 1.2176x; 1.0119x over previous
#include <cuda_runtime.h>
#include <cuda_fp16.h>
#include <math.h>
#include <stdint.h>

#define NB 32
#define NT 512
#define NI 1024
#define NH 1024
#define NG 4096
#define GB (NG*NB)              // gate elems per step, layout [t][j'][b]
#define LOFF (4*NH*NI)
#define GRID_BLOCKS 128
#define NK16 64                 // K=1024 in 64 chunks of 16
#define B_B32 16384             // one B vector in b32: 64*4*32*2 (fp16 single)
#define MAT_U4 524288           // uint4 stride per A matrix (4096x1024 fp16)
#define MAT_U32 2097152         // uint32 stride per A matrix
// smem: sA 8192 u4 (128K) + sB 16384 b32 (64K) + sTile 2048 f (8K)
//       + sC 512 f (2K) + sH 256 u32 (1K)
#define SMEM_BYTES (131072 + 65536 + 8192 + 2048 + 1024)
#define PRE_SMEM 32768

// ---------------- device scratch -------------------------------------------
__device__ __align__(256) float g_xg0[(size_t)(NT + 1) * GB]; // [t][j'][b]
// A fragments fp16 in m16n8k16 A layout.
// mats 0-2 (Wh0, Wh1, Wx1): interleaved rows j'=hh*4+g, [blk64][tile4][k16][lane]
// mat 3 (Wx0, pregemm): original rows, [blk32][warp8][k16][lane]
__device__ __align__(128) __half g_Ahi[(size_t)4 * 4096 * 1024];
__device__ __align__(128) __half g_Alo[(size_t)4 * 4096 * 1024]; // mat3 slot used
// seq B-fragments (hi only)
__device__ __align__(128) __half g_Sh[(size_t)64 * 2048 * 128];
// h B-fragments (single fp16), double-buffered by parity
__device__ __align__(128) uint32_t g_B0[2][B_B32];
__device__ __align__(128) uint32_t g_B1[2][B_B32];
// Wx1 @ h0 partial gate sums, double-buffered by parity: [p][j'][b]
__device__ __align__(256) float g_part[2][NG * NB];
__device__ unsigned g_bar_count;

// ---------------------------------------------------------------------------
__global__ void init_state() {
    int i = blockIdx.x * blockDim.x + threadIdx.x;
    int n = gridDim.x * blockDim.x;
    for (int k = i; k < B_B32; k += n) {
        g_B0[0][k] = 0u; g_B0[1][k] = 0u;
        g_B1[0][k] = 0u; g_B1[1][k] = 0u;
    }
    if (i == 0) g_bar_count = 0;
}

// ---------------------------------------------------------------------------
// Weights -> fp16 A-fragments, COALESCED: one thread per output uint32.
// ---------------------------------------------------------------------------
__global__ __launch_bounds__(256) void prep_weights(const float* __restrict__ Wh,
                                                    const float* __restrict__ Wx) {
    size_t i = (size_t)blockIdx.x * 256 + threadIdx.x;   // 0 .. 4*2M-1
    int r = (int)(i >> 21);
    int rem = (int)(i & (MAT_U32 - 1));
    int reg = rem & 3;
    int lane = (rem >> 2) & 31;
    int k16 = (rem >> 7) & 63;
    int T = rem >> 13;                 // 0..255
    int row16 = (lane >> 2) | ((reg & 1) << 3);
    int kc0 = 2 * (lane & 3) + ((reg >> 1) << 3);
    int k = k16 * 16 + kc0;

    int j;                              // source row
    if (r == 3) {
        j = T * 16 + row16;
    } else {
        int jp = T * 16 + row16;        // interleaved row j' = hh*4+g
        j = (jp & 3) * 1024 + (jp >> 2);
    }
    const float* src = (r == 0) ? Wh : (r == 1) ? (Wh + LOFF)
                     : (r == 2) ? (Wx + LOFF) : Wx;
    float2 w = *(const float2*)(src + (size_t)j * NI + k);

    __half h0 = __float2half_rn(w.x);
    __half h1 = __float2half_rn(w.y);
    ((__half2*)g_Ahi)[i] = __halves2half2(h0, h1);
    if (r == 3) {
        __half l0 = __float2half_rn(w.x - __half2float(h0));
        __half l1 = __float2half_rn(w.y - __half2float(h1));
        ((__half2*)g_Alo)[i] = __halves2half2(l0, l1);   // mat3 slot (offset in i)
    }
}

// ---------------------------------------------------------------------------
// seq -> fp16 B-fragments, COALESCED: one thread per output uint32.
// ---------------------------------------------------------------------------
__global__ __launch_bounds__(256) void prep_seq(const float* __restrict__ seq) {
    size_t i = (size_t)blockIdx.x * 256 + threadIdx.x;   // 0 .. 8M-1
    int reg = (int)(i & 1);
    int lane = (int)(i >> 1) & 31;
    int n8 = (int)(i >> 6) & 2047;
    int k16 = (int)(i >> 17);
    int nc = lane >> 2;
    int kc0 = 2 * (lane & 3) + (reg << 3);
    int c = n8 * 8 + nc;
    int t = c >> 5;
    int b = c & 31;
    int k = k16 * 16 + kc0;
    float2 v = *(const float2*)(seq + ((size_t)b * NT + t) * NI + k);
    ((__half2*)g_Sh)[i] = __halves2half2(__float2half_rn(v.x),
                                         __float2half_rn(v.y));
}

// ---------------------------------------------------------------------------
__device__ __forceinline__ void mma_f16(float* d, const uint4& a,
                                        uint32_t b0, uint32_t b1) {
    asm volatile(
        "mma.sync.aligned.m16n8k16.row.col.f32.f16.f16.f32 "
        "{%0,%1,%2,%3},{%4,%5,%6,%7},{%8,%9},{%0,%1,%2,%3};"
        : "+f"(d[0]), "+f"(d[1]), "+f"(d[2]), "+f"(d[3])
        : "r"(a.x), "r"(a.y), "r"(a.z), "r"(a.w), "r"(b0), "r"(b1));
}
__device__ __forceinline__ uint32_t smem_u32(const void* p) {
    uint32_t a;
    asm("{ .reg .u64 t; cvta.to.shared.u64 t, %1; cvt.u32.u64 %0, t; }"
        : "=r"(a) : "l"(p));
    return a;
}
__device__ __forceinline__ void cp16(uint32_t dst, const void* src) {
    asm volatile("cp.async.cg.shared.global [%0], [%1], 16;"
                 :: "r"(dst), "l"(src));
}
#define CP_COMMIT() asm volatile("cp.async.commit_group;")
#define CP_WAIT0()  asm volatile("cp.async.wait_group 0;")

// ---------------------------------------------------------------------------
// Pregemm: xg0[t][j'][b] = Wx0 @ x, fp16 2-pass (A hi/lo, B single fp16).
// Pointer arithmetic identical to R12 (full-size g_Alo + 3*MAT_U4 offset)
// to restore the faster codegen (regs 128, tensor 77%).
// ---------------------------------------------------------------------------
__global__ __launch_bounds__(256) void pregemm_mma() {
    extern __shared__ uint32_t sm[];
    uint32_t* sBh = sm;

    int tid = threadIdx.x;
    int lane = tid & 31;
    int wrp = tid >> 5;
    int blkM = blockIdx.x;
    int blkN = blockIdx.y;

    const uint4* Ah_w = (const uint4*)g_Ahi + 3 * MAT_U4 +
        (size_t)(blkM * 8 + wrp) * NK16 * 32;
    const uint4* Al_w = (const uint4*)g_Alo + 3 * MAT_U4 +
        (size_t)(blkM * 8 + wrp) * NK16 * 32;
    const uint4* gSh = (const uint4*)g_Sh;

    float acc[16][4];
#pragma unroll
    for (int nn = 0; nn < 16; nn++)
#pragma unroll
        for (int q = 0; q < 4; q++) acc[nn][q] = 0.0f;

    for (int kc8 = 0; kc8 < 8; kc8++) {
#pragma unroll
        for (int it = 0; it < 8; it++) {
            int flat = it * 256 + tid;
            int kk = flat >> 8;
            int rem = flat & 255;
            int nn = rem >> 4;
            int q = rem & 15;
            size_t srcu4 = ((size_t)(kc8 * 8 + kk) * 2048 + blkN * 16 + nn) * 16 + q;
            ((uint4*)sBh)[flat] = gSh[srcu4];
        }
        __syncthreads();
#pragma unroll 2
        for (int kk = 0; kk < 8; kk++) {
            int k16 = kc8 * 8 + kk;
            uint4 ah = Ah_w[k16 * 32 + lane];
            uint4 al = Al_w[k16 * 32 + lane];
#pragma unroll
            for (int nn = 0; nn < 16; nn++) {
                int bix = ((kk * 16 + nn) * 32 + lane) * 2;
                mma_f16(acc[nn], ah, sBh[bix], sBh[bix + 1]);
            }
#pragma unroll
            for (int nn = 0; nn < 16; nn++) {
                int bix = ((kk * 16 + nn) * 32 + lane) * 2;
                mma_f16(acc[nn], al, sBh[bix], sBh[bix + 1]);
            }
        }
        __syncthreads();
    }
    int j0a = blkM * 128 + wrp * 16 + (lane >> 2);
    int j0b = j0a + 8;
    int ja = (j0a & 1023) * 4 + (j0a >> 10);
    int jb = (j0b & 1023) * 4 + (j0b >> 10);
    int ccl = (lane & 3) * 2;
#pragma unroll
    for (int nn = 0; nn < 16; nn++) {
        int c = blkN * 128 + nn * 8 + ccl;
        int t = c >> 5;
        int b = c & 31;
        float* base = g_xg0 + (size_t)t * GB + b;
        *(float2*)(base + (size_t)ja * 32) = make_float2(acc[nn][0], acc[nn][1]);
        *(float2*)(base + (size_t)jb * 32) = make_float2(acc[nn][2], acc[nn][3]);
    }
}

// ---------------------------------------------------------------------------
__device__ __forceinline__ float sigf(float x) {
    return 1.0f / (1.0f + __expf(-x));
}
__device__ __forceinline__ float tanhfast(float x) {
    return 2.0f / (1.0f + __expf(-2.0f * x)) - 1.0f;
}

// monotonic grid barrier: REDG arrival (no return), acquire-poll by tid 0
__device__ __forceinline__ void grid_sync(unsigned& target) {
    __syncthreads();
    target += GRID_BLOCKS;
    if (threadIdx.x == 0) {
        asm volatile("red.release.gpu.global.add.u32 [%0], %1;"
                     :: "l"(&g_bar_count), "r"(1u) : "memory");
        unsigned v;
        do {
            asm volatile("ld.acquire.gpu.global.u32 %0, [%1];"
                         : "=r"(v) : "l"(&g_bar_count) : "memory");
        } while (v < target);
    }
    __syncthreads();
}

// write h (single fp16) into this block's smem fragment chunk (local hh 0..15)
__device__ __forceinline__ void store_h_sm(uint32_t* sH, int b, int hh_l, float hn) {
    int kc = hh_l;                       // hh_l < 16 -> kc == hh_l
    int n8 = b >> 3;
    int nc = b & 7;
    int lane = nc * 4 + ((kc & 7) >> 1);
    int reg = (kc >= 8) ? 1 : 0;
    int idx = (((n8 * 32 + lane) * 2 + reg) << 1) + (kc & 1);
    ((__half*)sH)[idx] = __float2half_rn(hn);
}

// swap register-index bit (1<<R) of v[16] with lane bit (1<<L)
template <int R, int L>
__device__ __forceinline__ void frag_swap(float* v, int lane) {
    bool a = (lane >> L) & 1;
#pragma unroll
    for (int i = 0; i < 16; i++) {
        if (i & (1 << R)) continue;
        int j = i | (1 << R);
        float send = a ? v[i] : v[j];
        float got = __shfl_xor_sync(0xffffffffu, send, 1 << L);
        if (a) v[i] = got; else v[j] = got;
    }
}

// ---------------------------------------------------------------------------
// Persistent LSTM (R12 structure): 128 blocks x 256 threads, monotonic REDG
// barrier, 513 rounds, L1 lags L0 by one round.  h publish is now smem-
// assembled then COALESCED (block blk owns exactly one 256-u32 k16 chunk).
//   L0 (bid 0..63): round n: stage h0(n) once; warps 0-3 Wh0 (pinned) @ h0 ->
//     shuffle-transpose -> in-register cell update -> sH -> coalesced publish;
//     warps 4-7 Wx1 (streamed) @ h0 -> g_part.  xr prefetched PRE-barrier.
//   L1 (bid 64..127): round s, m=s-1: stage h1(m-1); Wh1 (pinned) @ h1 ->
//     sTile combine; gates = sTile + g_part[m&1] + bias -> sH -> publish.
// ---------------------------------------------------------------------------
__global__ __launch_bounds__(256, 1) void lstm_persist(
    const float* __restrict__ Bias, float* __restrict__ out) {
    extern __shared__ uint32_t sm[];
    uint4* sA = (uint4*)sm;                      // 8192 u4 = 128 KB pinned A
    uint32_t* sB = sm + 32768;                   // 16384 b32 = 64 KB
    float* sTile = (float*)(sm + 49152);         // 2048 f32 (L1 only)
    float* sC = sTile + 2048;                    // 512 f32  (L1 only)
    uint32_t* sH1 = (uint32_t*)(sC + 512);       // 256 u32  (L1 publish)
    uint32_t* sH0 = (uint32_t*)sTile;            // L0 publish reuses sTile

    int tid = threadIdx.x;
    int lane = tid & 31;
    int wrp = tid >> 5;
    int bid = blockIdx.x;
    int region = (bid < 64) ? 0 : 1;
    int blk = bid & 63;
    uint32_t sBaddr = smem_u32(sB);

    // preload pinned A slice (mat0=Wh0 for L0, mat1=Wh1 for L1), 8192 uint4
    {
        const uint4* Apin = (const uint4*)g_Ahi +
            (size_t)region * MAT_U4 + (size_t)(blk * 4) * NK16 * 32;
        for (int i = tid; i < 8192; i += 256) sA[i] = Apin[i];
    }

    int tile = wrp & 3;
    int mat = wrp >> 2;   // L0: 0=Wh0 (pinned), 1=Wx1 (streamed); L1: khalf

    const uint4* A2 = (const uint4*)g_Ahi + 2 * MAT_U4 +
        (size_t)(blk * 4 + tile) * NK16 * 32;    // Wx1 slice (L0 warps 4-7)

    unsigned target = 0;

    if (region == 0) {
        // ------------------------------ LAYER 0 ------------------------------
        int colb = ((lane >> 2) & 3) * 8 + (lane & 3) * 2;
        float bgr[4][2];
        float creg[4];
        if (mat == 0) {
#pragma unroll
            for (int g = 0; g < 4; g++)
#pragma unroll
                for (int h2 = 0; h2 < 2; h2++) {
                    int hh_l = tile * 4 + (lane >> 4) + 2 * h2;
                    bgr[g][h2] = Bias[g * 1024 + blk * 16 + hh_l];
                }
            // prologue: h0(0) = cell(c=0, xg0[0] + bias) -> sH
            const float* xg = g_xg0 + (size_t)(blk * 64) * 32;
#pragma unroll
            for (int h2 = 0; h2 < 2; h2++) {
                int hh_l = tile * 4 + (lane >> 4) + 2 * h2;
#pragma unroll
                for (int cp = 0; cp < 2; cp++) {
                    int col = colb + cp;
                    float w = xg[(4 * hh_l + 1) * 32 + col] + bgr[1][h2];
                    float i_ = xg[(4 * hh_l + 2) * 32 + col] + bgr[2][h2];
                    float o = xg[(4 * hh_l + 3) * 32 + col] + bgr[3][h2];
                    float cn = sigf(w) * tanhfast(i_);
                    float hn = tanhfast(cn) * sigf(o);
                    creg[h2 * 2 + cp] = cn;
                    store_h_sm(sH0, col, hh_l, hn);
                }
            }
        }
        __syncthreads();
        g_B0[0][blk * 256 + tid] = sH0[tid];     // coalesced prologue publish

        for (int n = 0; n < NT; n++) {
            // PRE-barrier: prefetch next-step input gates (static data)
            float2 xr2[8];
            if (mat == 0 && n < NT - 1) {
                const float* xg = g_xg0 + (size_t)(n + 1) * GB +
                                  (size_t)(blk * 64) * 32;
#pragma unroll
                for (int g = 0; g < 4; g++)
#pragma unroll
                    for (int h2 = 0; h2 < 2; h2++) {
                        int hh_l = tile * 4 + (lane >> 4) + 2 * h2;
                        xr2[g * 2 + h2] =
                            *(const float2*)(xg + (size_t)(4 * hh_l + g) * 32 + colb);
                    }
            }
            grid_sync(target);
            int p = n & 1;
            // stage h0(n) fragments (64 KB)
            {
                const uint32_t* src = g_B0[p];
#pragma unroll
                for (int i = 0; i < 16; i++) {
                    int u = tid + i * 256;
                    cp16(sBaddr + u * 16, src + u * 4);
                }
                CP_COMMIT();
                CP_WAIT0();
            }
            __syncthreads();

            float accf[16];
#pragma unroll
            for (int i = 0; i < 16; i++) accf[i] = 0.0f;

            if (mat == 0) {
                if (n < NT - 1) {
#pragma unroll 8
                    for (int k16 = 0; k16 < NK16; k16++) {
                        uint4 a = sA[(tile * 64 + k16) * 32 + lane];
#pragma unroll
                        for (int nt = 0; nt < 4; nt++) {
                            int bix = (k16 * 4 + nt) * 64 + lane * 2;
                            mma_f16(&accf[nt * 4], a, sB[bix], sB[bix + 1]);
                        }
                    }
                    // shuffle-transpose: reg bits 2,3 (nt) <-> lane bits 2,3 (g)
                    frag_swap<2, 2>(accf, lane);
                    frag_swap<3, 3>(accf, lane);
                    // in-register cell update -> sH
#pragma unroll
                    for (int q = 0; q < 4; q++) {
                        int h2 = q >> 1, cp = q & 1;
                        int hh_l = tile * 4 + (lane >> 4) + 2 * h2;
                        int col = colb + cp;
                        float xf = cp ? xr2[0 * 2 + h2].y : xr2[0 * 2 + h2].x;
                        float xw = cp ? xr2[1 * 2 + h2].y : xr2[1 * 2 + h2].x;
                        float xi = cp ? xr2[2 * 2 + h2].y : xr2[2 * 2 + h2].x;
                        float xo = cp ? xr2[3 * 2 + h2].y : xr2[3 * 2 + h2].x;
                        float f = accf[0 + q] + xf + bgr[0][h2];
                        float w = accf[4 + q] + xw + bgr[1][h2];
                        float i_ = accf[8 + q] + xi + bgr[2][h2];
                        float o = accf[12 + q] + xo + bgr[3][h2];
                        float cv = creg[q];
                        float cn = cv * sigf(f) + sigf(w) * tanhfast(i_);
                        float hn = tanhfast(cn) * sigf(o);
                        creg[q] = cn;
                        store_h_sm(sH0, col, hh_l, hn);
                    }
                }
            } else {
                // Wx1 @ h0(n) -> partial gates for L1 next round
#pragma unroll 8
                for (int k16 = 0; k16 < NK16; k16++) {
                    uint4 a = A2[k16 * 32 + lane];
#pragma unroll
                    for (int nt = 0; nt < 4; nt++) {
                        int bix = (k16 * 4 + nt) * 64 + lane * 2;
                        mma_f16(&accf[nt * 4], a, sB[bix], sB[bix + 1]);
                    }
                }
                int r0 = tile * 16 + (lane >> 2);
                int cc = (lane & 3) * 2;
                float* gp = g_part[p] + (size_t)(blk * 64) * 32;
#pragma unroll
                for (int nt = 0; nt < 4; nt++) {
                    *(float2*)(gp + (size_t)r0 * 32 + nt * 8 + cc) =
                        make_float2(accf[nt * 4 + 0], accf[nt * 4 + 1]);
                    *(float2*)(gp + (size_t)(r0 + 8) * 32 + nt * 8 + cc) =
                        make_float2(accf[nt * 4 + 2], accf[nt * 4 + 3]);
                }
            }
            __syncthreads();
            if (n < NT - 1)
                g_B0[(n + 1) & 1][blk * 256 + tid] = sH0[tid];  // coalesced publish
        }
        grid_sync(target);                       // round s = NT (L1 finishes)
    } else {
        // ------------------------------ LAYER 1 ------------------------------
        float bf[2], bw[2], bi_[2], bo[2];
#pragma unroll
        for (int i = 0; i < 2; i++) {
            int hh = blk * 16 + ((tid + i * 256) >> 5);
            bf[i] = Bias[4096 + hh];        bw[i] = Bias[4096 + 1024 + hh];
            bi_[i] = Bias[4096 + 2048 + hh]; bo[i] = Bias[4096 + 3072 + hh];
        }
#pragma unroll
        for (int i = 0; i < 2; i++) sC[tid + i * 256] = 0.0f;
        __syncthreads();

        for (int s = 0; s <= NT; s++) {
            grid_sync(target);
            if (s < 1) continue;
            int m = s - 1;
            if (m >= 1) {
                // stage h1(m-1) (64 KB)
                {
                    const uint32_t* src = g_B1[(m - 1) & 1];
#pragma unroll
                    for (int i = 0; i < 16; i++) {
                        int u = tid + i * 256;
                        cp16(sBaddr + u * 16, src + u * 4);
                    }
                    CP_COMMIT();
                    CP_WAIT0();
                }
                __syncthreads();

                float accf[16];
#pragma unroll
                for (int i = 0; i < 16; i++) accf[i] = 0.0f;
#pragma unroll 8
                for (int kk = 0; kk < 32; kk++) {
                    int k16 = mat * 32 + kk;
                    uint4 a = sA[(tile * 64 + k16) * 32 + lane];
#pragma unroll
                    for (int nt = 0; nt < 4; nt++) {
                        int bix = (k16 * 4 + nt) * 64 + lane * 2;
                        mma_f16(&accf[nt * 4], a, sB[bix], sB[bix + 1]);
                    }
                }
                // combine K-halves in sTile
                int r0 = tile * 16 + (lane >> 2);
                int cc = (lane & 3) * 2;
                if (mat == 0) {
#pragma unroll
                    for (int nt = 0; nt < 4; nt++) {
                        *(float2*)&sTile[r0 * 32 + nt * 8 + cc] =
                            make_float2(accf[nt * 4 + 0], accf[nt * 4 + 1]);
                        *(float2*)&sTile[(r0 + 8) * 32 + nt * 8 + cc] =
                            make_float2(accf[nt * 4 + 2], accf[nt * 4 + 3]);
                    }
                }
                __syncthreads();
                if (mat == 1) {
#pragma unroll
                    for (int nt = 0; nt < 4; nt++) {
                        float2* p0 = (float2*)&sTile[r0 * 32 + nt * 8 + cc];
                        float2* p1 = (float2*)&sTile[(r0 + 8) * 32 + nt * 8 + cc];
                        float2 v0 = *p0, v1 = *p1;
                        v0.x += accf[nt * 4 + 0]; v0.y += accf[nt * 4 + 1];
                        v1.x += accf[nt * 4 + 2]; v1.y += accf[nt * 4 + 3];
                        *p0 = v0; *p1 = v1;
                    }
                }
                __syncthreads();
            } else {
                // m == 0: h1(-1) = 0, recurrent term vanishes
                for (int i = tid; i < 2048; i += 256) sTile[i] = 0.0f;
                __syncthreads();
            }
            // fused cell update: gates = sTile + partial(m) + bias -> sH1
            const float* gp = g_part[m & 1] + (size_t)(blk * 64) * 32;
#pragma unroll
            for (int i = 0; i < 2; i++) {
                int q = tid + i * 256;
                int hh_l = q >> 5, b = q & 31, br = hh_l * 4;
                float f = sTile[br * 32 + b] + gp[br * 32 + b] + bf[i];
                float w = sTile[(br + 1) * 32 + b] + gp[(br + 1) * 32 + b] + bw[i];
                float i_ = sTile[(br + 2) * 32 + b] + gp[(br + 2) * 32 + b] + bi_[i];
                float o = sTile[(br + 3) * 32 + b] + gp[(br + 3) * 32 + b] + bo[i];
                float cv = sC[q];
                float cn = cv * sigf(f) + sigf(w) * tanhfast(i_);
                float hn = tanhfast(cn) * sigf(o);
                sC[q] = cn;
                store_h_sm(sH1, b, hh_l, hn);
                if (m == NT - 1) out[b * 1024 + blk * 16 + hh_l] = hn;
            }
            __syncthreads();
            g_B1[m & 1][blk * 256 + tid] = sH1[tid];  // coalesced publish
        }
    }
}

// ---------------------------------------------------------------------------
extern "C" void kernel_launch(void* const* d_in, const int* in_sizes, int n_in,
                              void* d_out, int out_size) {
    const float* seq  = (const float*)d_in[0];  // (32, 512, 1024)
    const float* Wh   = (const float*)d_in[1];  // (2, 4, 1024, 1024)
    const float* Wx   = (const float*)d_in[2];  // (2, 4, 1024, 1024)
    const float* Bias = (const float*)d_in[3];  // (2, 4, 1024)
    float* out = (float*)d_out;                 // (32, 1024)

    cudaFuncSetAttribute(lstm_persist,
                         cudaFuncAttributeMaxDynamicSharedMemorySize, SMEM_BYTES);
    cudaFuncSetAttribute(pregemm_mma,
                         cudaFuncAttributeMaxDynamicSharedMemorySize, PRE_SMEM);

    init_state<<<64, 256>>>();
    prep_weights<<<4 * MAT_U32 / 256, 256>>>(Wh, Wx);
    prep_seq<<<8 * 1024 * 1024 / 256, 256>>>(seq);
    pregemm_mma<<<dim3(32, 128), 256, PRE_SMEM>>>();
    lstm_persist<<<GRID_BLOCKS, 256, SMEM_BYTES>>>(Bias, out);
}